// round 11
// baseline (speedup 1.0000x reference)
#include <cuda_runtime.h>
#include <cuda_fp16.h>
#include <math.h>
#include <stdint.h>

#define NB 32768
#define HD 512
#define DV 256
#define NP 512
#define RHO_MAXF 9.0f
#define DELTAF 0.001f
#define EPSF 1e-8f
#define PIF 3.14159265358979f

// ---------------- scratch (__device__ globals: no allocations allowed) ----------------
__device__ __half g_hEnt[NB*HD];
__device__ __half g_hRel[NB*HD];
__device__ __half g_hLab[NB*HD];
__device__ __half g_hH0[NB*HD];
__device__ __half g_hH1[NB*HD];
__device__ __half g_hH2[NB*HD];
__device__ __half g_hEh[NB*HD];
__device__ __half g_hEr[NB*HD];
__device__ __half g_hEt[NB*HD];
__device__ __half g_hW1[HD*HD];
__device__ __half g_hW2[HD*HD];
__device__ __half g_hWv[DV*HD];
__device__ __half g_hWt[NP*HD];
__device__ float g_Vh[NB*DV];
__device__ float g_Vt[NB*DV];
__device__ float g_TH[NB*NP];
__device__ float g_thT[NP*NB];
__device__ float g_uhT[DV*NB];
__device__ float g_utT[DV*NB];
__device__ float g_urT[DV*NB];
__device__ float g_reh[NB];
__device__ float g_rrr[NB];
__device__ float g_ret[NB];

__device__ __forceinline__ float softplusf(float x) {
    return (x > 20.f) ? x : log1pf(expf(x));
}

__device__ __forceinline__ float fast_tanh(float x) {
    float y;
    asm("tanh.approx.f32 %0, %1;" : "=f"(y) : "f"(x));
    return y;
}

#define CP_ASYNC16(dst, src) \
    asm volatile("cp.async.cg.shared.global [%0], [%1], 16;" :: "r"(dst), "l"(src))
#define CP_COMMIT() asm volatile("cp.async.commit_group;" ::: "memory")
#define CP_WAITG2() asm volatile("cp.async.wait_group 2;" ::: "memory")

#define LDSM4(r0, r1, r2, r3, addr) \
    asm volatile("ldmatrix.sync.aligned.m8n8.x4.shared.b16 {%0,%1,%2,%3}, [%4];" \
                 : "=r"(r0), "=r"(r1), "=r"(r2), "=r"(r3) : "r"(addr))

__device__ __forceinline__ uint32_t smem_u32(const void* p) {
    uint32_t a;
    asm("{ .reg .u64 t; cvta.to.shared.u64 t, %1; cvt.u32.u64 %0, t; }" : "=r"(a) : "l"(p));
    return a;
}

// ---------------- fp32 -> fp16 conversions -------------------------------------------
__global__ void cvt3_f2h(const float* __restrict__ s0, const float* __restrict__ s1,
                         const float* __restrict__ s2,
                         __half* __restrict__ d0, __half* __restrict__ d1,
                         __half* __restrict__ d2)
{
    const float* s = (blockIdx.y == 0) ? s0 : (blockIdx.y == 1) ? s1 : s2;
    __half* d = (blockIdx.y == 0) ? d0 : (blockIdx.y == 1) ? d1 : d2;
    const int i = (blockIdx.x * blockDim.x + threadIdx.x) * 8;
    float4 a = *(const float4*)&s[i];
    float4 b = *(const float4*)&s[i + 4];
    __half2 h0 = __floats2half2_rn(a.x, a.y);
    __half2 h1 = __floats2half2_rn(a.z, a.w);
    __half2 h2 = __floats2half2_rn(b.x, b.y);
    __half2 h3 = __floats2half2_rn(b.z, b.w);
    uint4 o;
    o.x = *(uint32_t*)&h0; o.y = *(uint32_t*)&h1;
    o.z = *(uint32_t*)&h2; o.w = *(uint32_t*)&h3;
    *(uint4*)&d[i] = o;
}

__global__ void cvt_f2h(const float* __restrict__ src, __half* __restrict__ dst, int n)
{
    const int i = (blockIdx.x * blockDim.x + threadIdx.x) * 8;
    if (i >= n) return;
    float4 a = *(const float4*)&src[i];
    float4 b = *(const float4*)&src[i + 4];
    __half2 h0 = __floats2half2_rn(a.x, a.y);
    __half2 h1 = __floats2half2_rn(a.z, a.w);
    __half2 h2 = __floats2half2_rn(b.x, b.y);
    __half2 h3 = __floats2half2_rn(b.z, b.w);
    uint4 o;
    o.x = *(uint32_t*)&h0; o.y = *(uint32_t*)&h1;
    o.z = *(uint32_t*)&h2; o.w = *(uint32_t*)&h3;
    *(uint4*)&dst[i] = o;
}

// ---------------- FP16 tensor-core NT GEMM (m16n8k16 + ldmatrix, 4-stage, 1 sync) ----
// C[M,N] = A[M,512] * W[N,512]^T + bias, fp32 accumulate.
// Block 128M x 128N, 8 warps (4m x 2n), warp tile 32x64, KTILE=32 (2 k16 steps),
// 4-stage cp.async pipeline, ONE __syncthreads per iteration. Smem stride 20 words.
// mode bits: 1=relu, 2=+residual(fp32), 4=store fp32 C, 8=store fp16 Ch
#define SMS 20
#define KDIM 512
#define KT 32
#define NKT (KDIM / KT)            // 16
#define SA_WORDS (128 * SMS)       // 2560
#define STG_WORDS (2 * SA_WORDS)   // 5120
#define STG_BYTES (STG_WORDS * 4)  // 20480
#define GEMM_SMEM_BYTES (4 * STG_BYTES)   // 81920

__global__ __launch_bounds__(256, 2)
void gemm_h(const __half* __restrict__ A0, const __half* __restrict__ A1,
            const __half* __restrict__ A2,
            const __half* __restrict__ W, const float* __restrict__ bias,
            const float* __restrict__ R0, const float* __restrict__ R1,
            const float* __restrict__ R2,
            float* __restrict__ C0, float* __restrict__ C1, float* __restrict__ C2,
            __half* __restrict__ Ch0, __half* __restrict__ Ch1, __half* __restrict__ Ch2,
            int N, int mode)
{
    extern __shared__ __align__(16) uint32_t smem[];
    const int tid = threadIdx.x, wid = tid >> 5, lane = tid & 31;
    const int g = lane >> 2, tg = lane & 3;
    const int z = blockIdx.z;
    const __half* A = (z == 0) ? A0 : (z == 1) ? A1 : A2;
    const float*  R = (z == 0) ? R0 : (z == 1) ? R1 : R2;
    float*        C = (z == 0) ? C0 : (z == 1) ? C1 : C2;
    __half*      Ch = (z == 0) ? Ch0 : (z == 1) ? Ch1 : Ch2;
    const int m0 = blockIdx.y * 128;
    const int n0 = blockIdx.x * 128;
    const int moff = (wid & 3) * 32;
    const int noff = (wid >> 2) * 64;
    const __half* Ag = A + (size_t)m0 * KDIM;
    const __half* Bg = W + (size_t)n0 * KDIM;

    const uint32_t sbase = smem_u32(smem);

    // ldmatrix per-lane addressing: row-in-group + k-half select
    const int lrow8 = ((lane >> 3) & 1) * 8 + (lane & 7);
    const int lk4   = (lane >> 4) * 4;          // word offset: 0 or 4
    uint32_t aoff[2], boff[4];
    #pragma unroll
    for (int mt = 0; mt < 2; mt++)
        aoff[mt] = ((moff + mt * 16 + lrow8) * SMS + lk4) * 4;
    #pragma unroll
    for (int ntp = 0; ntp < 4; ntp++)
        boff[ntp] = ((noff + ntp * 16 + lrow8) * SMS + lk4) * 4;

    float acc[2][8][4];
    #pragma unroll
    for (int mt = 0; mt < 2; mt++)
        #pragma unroll
        for (int nt = 0; nt < 8; nt++)
            #pragma unroll
            for (int q = 0; q < 4; q++) acc[mt][nt][q] = 0.f;

    #define FILL_STAGE(stg, k0)                                                      \
    do {                                                                             \
        const uint32_t wA = sbase + (stg) * STG_BYTES;                               \
        const uint32_t wB = wA + SA_WORDS * 4;                                       \
        _Pragma("unroll")                                                            \
        for (int p = 0; p < 2; p++) {                                                \
            const int c = tid + 256 * p;                                             \
            const int row = c >> 2;                                                  \
            CP_ASYNC16(wA + (row * SMS + (c & 3) * 4) * 4,                           \
                       &Ag[(size_t)row * KDIM + (k0) + (c & 3) * 8]);                \
            CP_ASYNC16(wB + (row * SMS + (c & 3) * 4) * 4,                           \
                       &Bg[(size_t)row * KDIM + (k0) + (c & 3) * 8]);                \
        }                                                                            \
    } while (0)

    FILL_STAGE(0, 0);      CP_COMMIT();
    FILL_STAGE(1, KT);     CP_COMMIT();
    FILL_STAGE(2, 2 * KT); CP_COMMIT();

    for (int t = 0; t < NKT; t++) {
        CP_WAITG2();              // pending {t, t+1, t+2} -> fill(t) resident
        __syncthreads();          // all warps done compute(t-1): stage (t+3)&3 is free
        if (t + 3 < NKT) { FILL_STAGE((t + 3) & 3, (t + 3) * KT); }
        CP_COMMIT();              // uniform group counting (empty commit at tail)

        const uint32_t Ab = sbase + (t & 3) * STG_BYTES;
        const uint32_t Bb = Ab + SA_WORDS * 4;

        #pragma unroll
        for (int ks = 0; ks < 2; ks++) {
            const uint32_t kb4 = ks * 32;     // k16 half: 8 words = 32 bytes
            uint32_t af[2][4], bf[8][2];
            #pragma unroll
            for (int mt = 0; mt < 2; mt++)
                LDSM4(af[mt][0], af[mt][1], af[mt][2], af[mt][3], Ab + aoff[mt] + kb4);
            #pragma unroll
            for (int ntp = 0; ntp < 4; ntp++)
                LDSM4(bf[2*ntp][0], bf[2*ntp+1][0], bf[2*ntp][1], bf[2*ntp+1][1],
                      Bb + boff[ntp] + kb4);
            #pragma unroll
            for (int mt = 0; mt < 2; mt++)
                #pragma unroll
                for (int nt = 0; nt < 8; nt++) {
                    asm volatile(
                        "mma.sync.aligned.m16n8k16.row.col.f32.f16.f16.f32 "
                        "{%0,%1,%2,%3}, {%4,%5,%6,%7}, {%8,%9}, {%0,%1,%2,%3};"
                        : "+f"(acc[mt][nt][0]), "+f"(acc[mt][nt][1]),
                          "+f"(acc[mt][nt][2]), "+f"(acc[mt][nt][3])
                        : "r"(af[mt][0]), "r"(af[mt][1]), "r"(af[mt][2]), "r"(af[mt][3]),
                          "r"(bf[nt][0]), "r"(bf[nt][1]));
                }
        }
    }

    // ---- epilogue (lean, unchanged from R9) ----
    #pragma unroll
    for (int mt = 0; mt < 2; mt++) {
        #pragma unroll
        for (int nt = 0; nt < 8; nt++) {
            const int n = n0 + noff + nt * 8 + 2 * tg;
            const int ra = m0 + moff + mt * 16 + g;
            const int rb = ra + 8;
            float bx = bias[n], by = bias[n + 1];
            float2 v0 = make_float2(acc[mt][nt][0] + bx, acc[mt][nt][1] + by);
            float2 v1 = make_float2(acc[mt][nt][2] + bx, acc[mt][nt][3] + by);
            if (mode & 1) {
                v0.x = fmaxf(v0.x, 0.f); v0.y = fmaxf(v0.y, 0.f);
                v1.x = fmaxf(v1.x, 0.f); v1.y = fmaxf(v1.y, 0.f);
            }
            if (mode & 2) {
                float2 r0v = *(const float2*)&R[(size_t)ra * N + n];
                float2 r1v = *(const float2*)&R[(size_t)rb * N + n];
                v0.x += r0v.x; v0.y += r0v.y;
                v1.x += r1v.x; v1.y += r1v.y;
            }
            if (mode & 4) {
                *(float2*)&C[(size_t)ra * N + n] = v0;
                *(float2*)&C[(size_t)rb * N + n] = v1;
            }
            if (mode & 8) {
                __half2 h0 = __floats2half2_rn(v0.x, v0.y);
                __half2 h1 = __floats2half2_rn(v1.x, v1.y);
                *(__half2*)&Ch[(size_t)ra * N + n] = h0;
                *(__half2*)&Ch[(size_t)rb * N + n] = h1;
            }
        }
    }
}

// ---------------- three N=1 GEMVs on fp16 E: re_h, rr_r, re_t ------------------------
__global__ void gemv3h(const __half* __restrict__ Eh, const __half* __restrict__ Er,
                       const __half* __restrict__ Et,
                       const float* __restrict__ Wre, const float* __restrict__ bre,
                       const float* __restrict__ Wrr, const float* __restrict__ brr,
                       float* __restrict__ reh, float* __restrict__ rrr, float* __restrict__ ret)
{
    const int warp = (blockIdx.x * blockDim.x + threadIdx.x) >> 5;
    const int lane = threadIdx.x & 31;
    if (warp >= NB) return;
    const __half* eh = Eh + (size_t)warp * HD;
    const __half* er = Er + (size_t)warp * HD;
    const __half* et = Et + (size_t)warp * HD;
    float s1 = 0.f, s2 = 0.f, s3 = 0.f;
    #pragma unroll
    for (int k = lane * 8; k < HD; k += 256) {
        uint4 a = *(const uint4*)&eh[k];
        uint4 b = *(const uint4*)&er[k];
        uint4 c = *(const uint4*)&et[k];
        #pragma unroll
        for (int j = 0; j < 4; j++) {
            float2 ea = __half22float2(*(const __half2*)((const uint32_t*)&a + j));
            float2 eb = __half22float2(*(const __half2*)((const uint32_t*)&b + j));
            float2 ec = __half22float2(*(const __half2*)((const uint32_t*)&c + j));
            float2 wre = *(const float2*)&Wre[k + 2 * j];
            float2 wrr = *(const float2*)&Wrr[k + 2 * j];
            s1 = fmaf(ea.x, wre.x, fmaf(ea.y, wre.y, s1));
            s2 = fmaf(eb.x, wrr.x, fmaf(eb.y, wrr.y, s2));
            s3 = fmaf(ec.x, wre.x, fmaf(ec.y, wre.y, s3));
        }
    }
    #pragma unroll
    for (int o = 16; o > 0; o >>= 1) {
        s1 += __shfl_down_sync(0xffffffffu, s1, o);
        s2 += __shfl_down_sync(0xffffffffu, s2, o);
        s3 += __shfl_down_sync(0xffffffffu, s3, o);
    }
    if (lane == 0) {
        reh[warp] = s1 + bre[0];
        rrr[warp] = s2 + brr[0];
        ret[warp] = s3 + bre[0];
    }
}

// ---------------- theta transpose: out[c, b] = pi * tanh(in[b, c]) --------------------
__global__ void transpose_th(const float* __restrict__ in, float* __restrict__ out)
{
    __shared__ float tile[32][33];
    const int tx = threadIdx.x, ty = threadIdx.y;
    const int x = blockIdx.x * 32 + tx;
    const int y0 = blockIdx.y * 32;
    #pragma unroll
    for (int j = ty; j < 32; j += 8)
        tile[j][tx] = in[(size_t)(y0 + j) * NP + x];
    __syncthreads();
    const int c0 = blockIdx.x * 32;
    #pragma unroll
    for (int j = ty; j < 32; j += 8) {
        float v = tile[tx][j];
        out[(size_t)(c0 + j) * NB + y0 + tx] = PIF * fast_tanh(v);
    }
}

// ---------------- fused l2-norm + transpose: outT[c, b] = in[b, c]/||in[b,:]|| --------
__global__ __launch_bounds__(256)
void transnorm(const float* __restrict__ in, float* __restrict__ outT)
{
    __shared__ float tile[32][DV + 1];
    __shared__ float rnorm[32];
    const int tid = threadIdx.x, wid = tid >> 5, lane = tid & 31;
    const int y0 = blockIdx.x * 32;

    #pragma unroll 4
    for (int i = 0; i < 32; i++)
        tile[i][tid] = in[(size_t)(y0 + i) * DV + tid];
    __syncthreads();

    #pragma unroll
    for (int rr = 0; rr < 4; rr++) {
        const int row = wid * 4 + rr;
        float s = 0.f;
        #pragma unroll
        for (int c = lane; c < DV; c += 32) { float v = tile[row][c]; s = fmaf(v, v, s); }
        #pragma unroll
        for (int o = 16; o > 0; o >>= 1) s += __shfl_down_sync(0xffffffffu, s, o);
        if (lane == 0) rnorm[row] = 1.f / (sqrtf(s) + EPSF);
    }
    __syncthreads();

    #pragma unroll 4
    for (int i = 0; i < 32; i++) {
        const int idx = tid + 256 * i;
        const int c = idx >> 5, bl = idx & 31;
        outT[(size_t)c * NB + y0 + bl] = tile[bl][c] * rnorm[bl];
    }
}

// ---------------- fused rotation + slerp + score --------------------------------------
__global__ void rot_score(
    const float* __restrict__ uhT, const float* __restrict__ utT,
    const float* __restrict__ thT, float* __restrict__ urT,
    const float* __restrict__ sim,
    const float* __restrict__ reh, const float* __restrict__ rrr, const float* __restrict__ ret,
    const float* __restrict__ ga_rho, const float* __restrict__ gb_rho,
    const float* __restrict__ ga_phi, const float* __restrict__ gb_phi,
    float* __restrict__ out)
{
    const int b = blockIdx.x * blockDim.x + threadIdx.x;
    if (b >= NB) return;

    float cur = uhT[b];
    float u0w = 0.f;
    #pragma unroll 4
    for (int i = 0; i < 255; i++) {
        float s, c; __sincosf(thT[(size_t)i * NB + b], &s, &c);
        float nxt = uhT[(size_t)(i + 1) * NB + b];
        float wi = c * cur - s * nxt;
        urT[(size_t)i * NB + b] = wi;
        if (i == 0) u0w = wi;
        cur = s * cur + c * nxt;
    }
    {
        float s, c; __sincosf(thT[(size_t)255 * NB + b], &s, &c);
        float w255 = c * cur - s * u0w;
        float w0   = s * cur + c * u0w;
        urT[(size_t)255 * NB + b] = w255;
        urT[b] = w0;
    }

    float dhr = 0.f, dht = 0.f, drt = 0.f, ssq = 0.f;
    const float uh0 = uhT[b], ut0 = utT[b];
    cur = urT[b];
    float w0sav = 0.f;
    #pragma unroll 4
    for (int i = 0; i < 255; i++) {
        float s, c; __sincosf(thT[(size_t)(256 + i) * NB + b], &s, &c);
        float nxt = urT[(size_t)(i + 1) * NB + b];
        float wi = c * cur - s * nxt;
        cur = s * cur + c * nxt;
        if (i == 0) {
            w0sav = wi;
        } else {
            float uh = uhT[(size_t)i * NB + b];
            float ut = utT[(size_t)i * NB + b];
            ssq += wi * wi; dhr += wi * uh; drt += wi * ut; dht += uh * ut;
        }
    }
    float w255f, w0f;
    {
        float s, c; __sincosf(thT[(size_t)511 * NB + b], &s, &c);
        w255f = c * cur - s * w0sav;
        w0f   = s * cur + c * w0sav;
    }
    {
        float uh255 = uhT[(size_t)255 * NB + b], ut255 = utT[(size_t)255 * NB + b];
        ssq += w255f * w255f + w0f * w0f;
        dhr += w255f * uh255 + w0f * uh0;
        drt += w255f * ut255 + w0f * ut0;
        dht += uh255 * ut255 + uh0 * ut0;
    }

    float nr = sqrtf(ssq);
    float inv_rot = 1.f / (nr + EPSF);
    float dhr_n = dhr * inv_rot;
    float dotc = fminf(fmaxf(dhr_n, -1.f + EPSF), 1.f - EPSF);
    float omega = acosf(dotc);
    float sin_om = sinf(omega);
    float sv = sim[b];
    float grho = 1.f / (1.f + expf(-(ga_rho[0] * sv + gb_rho[0])));
    float gphi = 1.f / (1.f + expf(-(ga_phi[0] * sv + gb_phi[0])));
    float ca, cb;
    if (omega > DELTAF) {
        float iso = 1.f / (sin_om + EPSF);
        ca = sinf((1.f - gphi) * omega) * iso;
        cb = sinf(gphi * omega) * iso;
    } else {
        ca = 1.f - gphi; cb = gphi;
    }
    float nrn = nr * inv_rot;
    float np2 = ca * ca + cb * cb * nrn * nrn + 2.f * ca * cb * dhr_n;
    float npv = sqrtf(fmaxf(np2, 0.f));
    float inv_np = 1.f / (npv + EPSF);
    float dpt = (ca * dht + cb * drt * inv_rot) * inv_np;

    float rho_h = fminf(softplusf(reh[b]), RHO_MAXF);
    float rho_p = fminf(fmaxf(rho_h + rrr[b] * grho, 0.f), RHO_MAXF);
    float rho_t = fminf(softplusf(ret[b]), RHO_MAXF);
    out[b] = -coshf(rho_p) * coshf(rho_t) + sinhf(rho_p) * sinhf(rho_t) * dpt;
}

// ---------------- launch --------------------------------------------------------------
extern "C" void kernel_launch(void* const* d_in, const int* in_sizes, int n_in,
                              void* d_out, int out_size)
{
    const float* ent  = (const float*)d_in[0];
    const float* rel  = (const float*)d_in[1];
    const float* lab  = (const float*)d_in[2];
    const float* sim  = (const float*)d_in[3];
    const float* Wv   = (const float*)d_in[4];
    const float* bv   = (const float*)d_in[5];
    const float* Wre  = (const float*)d_in[6];
    const float* bre  = (const float*)d_in[7];
    const float* Wrr  = (const float*)d_in[8];
    const float* brr  = (const float*)d_in[9];
    const float* Wt   = (const float*)d_in[10];
    const float* bt   = (const float*)d_in[11];
    const float* ga_rho = (const float*)d_in[12];
    const float* gb_rho = (const float*)d_in[13];
    const float* ga_phi = (const float*)d_in[14];
    const float* gb_phi = (const float*)d_in[15];
    const float* W1   = (const float*)d_in[16];
    const float* b1   = (const float*)d_in[17];
    const float* W2   = (const float*)d_in[18];
    const float* b2   = (const float*)d_in[19];
    float* out = (float*)d_out;

    __half *hEnt, *hRel, *hLab, *hH0, *hH1, *hH2, *hEh, *hEr, *hEt;
    __half *hW1, *hW2, *hWv, *hWt;
    float *Vh, *Vt, *TH, *thT, *uhT, *utT, *urT, *reh, *rrr, *ret;
    cudaGetSymbolAddress((void**)&hEnt, g_hEnt);
    cudaGetSymbolAddress((void**)&hRel, g_hRel);
    cudaGetSymbolAddress((void**)&hLab, g_hLab);
    cudaGetSymbolAddress((void**)&hH0,  g_hH0);
    cudaGetSymbolAddress((void**)&hH1,  g_hH1);
    cudaGetSymbolAddress((void**)&hH2,  g_hH2);
    cudaGetSymbolAddress((void**)&hEh,  g_hEh);
    cudaGetSymbolAddress((void**)&hEr,  g_hEr);
    cudaGetSymbolAddress((void**)&hEt,  g_hEt);
    cudaGetSymbolAddress((void**)&hW1,  g_hW1);
    cudaGetSymbolAddress((void**)&hW2,  g_hW2);
    cudaGetSymbolAddress((void**)&hWv,  g_hWv);
    cudaGetSymbolAddress((void**)&hWt,  g_hWt);
    cudaGetSymbolAddress((void**)&Vh,   g_Vh);
    cudaGetSymbolAddress((void**)&Vt,   g_Vt);
    cudaGetSymbolAddress((void**)&TH,   g_TH);
    cudaGetSymbolAddress((void**)&thT,  g_thT);
    cudaGetSymbolAddress((void**)&uhT,  g_uhT);
    cudaGetSymbolAddress((void**)&utT,  g_utT);
    cudaGetSymbolAddress((void**)&urT,  g_urT);
    cudaGetSymbolAddress((void**)&reh,  g_reh);
    cudaGetSymbolAddress((void**)&rrr,  g_rrr);
    cudaGetSymbolAddress((void**)&ret,  g_ret);

    cudaFuncSetAttribute(gemm_h, cudaFuncAttributeMaxDynamicSharedMemorySize,
                         GEMM_SMEM_BYTES);

    // fp32 -> fp16 conversions (inputs batched + weights)
    const int BIG = NB * HD;
    cvt3_f2h<<<dim3(BIG / (256 * 8), 3), 256>>>(ent, rel, lab, hEnt, hRel, hLab);
    cvt_f2h<<<(HD * HD) / (256 * 8), 256>>>(W1, hW1, HD * HD);
    cvt_f2h<<<(HD * HD) / (256 * 8), 256>>>(W2, hW2, HD * HD);
    cvt_f2h<<<(DV * HD) / (256 * 8), 256>>>(Wv, hWv, DV * HD);
    cvt_f2h<<<(NP * HD) / (256 * 8), 256>>>(Wt, hWt, NP * HD);

    const dim3 blk(256);
    // layer 1: hH_z = fp16(relu(X_z @ W1^T + b1))         mode 1|8 = 9
    gemm_h<<<dim3(HD/128, NB/128, 3), blk, GEMM_SMEM_BYTES>>>(
        hEnt, hRel, hLab, hW1, b1, nullptr, nullptr, nullptr,
        nullptr, nullptr, nullptr, hH0, hH1, hH2, HD, 9);
    // layer 2: hE_z = fp16(H_z @ W2^T + b2 + X_z)         mode 2|8 = 10
    gemm_h<<<dim3(HD/128, NB/128, 3), blk, GEMM_SMEM_BYTES>>>(
        hH0, hH1, hH2, hW2, b2, ent, rel, lab,
        nullptr, nullptr, nullptr, hEh, hEr, hEt, HD, 10);
    // Wv projections (fp32 out)                           mode 4
    gemm_h<<<dim3(DV/128, NB/128, 2), blk, GEMM_SMEM_BYTES>>>(
        hEh, hEt, nullptr, hWv, bv, nullptr, nullptr, nullptr,
        Vh, Vt, nullptr, nullptr, nullptr, nullptr, DV, 4);
    // theta logits (fp32 out)                             mode 4
    gemm_h<<<dim3(NP/128, NB/128, 1), blk, GEMM_SMEM_BYTES>>>(
        hEr, nullptr, nullptr, hWt, bt, nullptr, nullptr, nullptr,
        TH, nullptr, nullptr, nullptr, nullptr, nullptr, NP, 4);

    // scalar GEMVs (rho logits / delta_rho) on fp16 E
    gemv3h<<<NB / 8, 256>>>(hEh, hEr, hEt, Wre, bre, Wrr, brr, reh, rrr, ret);

    // transposes: thetas (pi*tanh) + normalized u vectors
    transpose_th<<<dim3(NP / 32, NB / 32), dim3(32, 8)>>>(TH, thT);
    transnorm<<<NB / 32, 256>>>(Vh, uhT);
    transnorm<<<NB / 32, 256>>>(Vt, utT);

    // fused Givens sweeps + slerp + hyperbolic score
    rot_score<<<NB / 256, 256>>>(uhT, utT, thT, urT, sim, reh, rrr, ret,
                                 ga_rho, gb_rho, ga_phi, gb_phi, out);
    (void)in_sizes; (void)n_in; (void)out_size;
}

// round 12
// speedup vs baseline: 1.0102x; 1.0102x over previous
#include <cuda_runtime.h>
#include <cuda_fp16.h>
#include <math.h>
#include <stdint.h>

#define NB 32768
#define HD 512
#define DV 256
#define NP 512
#define RHO_MAXF 9.0f
#define DELTAF 0.001f
#define EPSF 1e-8f
#define PIF 3.14159265358979f

// ---------------- scratch (__device__ globals: no allocations allowed) ----------------
__device__ __half g_hEnt[NB*HD];
__device__ __half g_hRel[NB*HD];
__device__ __half g_hLab[NB*HD];
__device__ __half g_hH0[NB*HD];
__device__ __half g_hH1[NB*HD];
__device__ __half g_hH2[NB*HD];
__device__ __half g_hEh[NB*HD];
__device__ __half g_hEr[NB*HD];
__device__ __half g_hEt[NB*HD];
__device__ __half g_hW1[HD*HD];
__device__ __half g_hW2[HD*HD];
__device__ __half g_hWv[DV*HD];
__device__ __half g_hWt[NP*HD];
__device__ float g_Vh[NB*DV];
__device__ float g_Vt[NB*DV];
__device__ float g_TH[NB*NP];
__device__ float2 g_scT[(size_t)NP*NB];   // transposed (sin, cos) of pi*tanh(TH)
__device__ float g_uhT[DV*NB];
__device__ float g_utT[DV*NB];
__device__ float g_urT[DV*NB];
__device__ float g_reh[NB];
__device__ float g_rrr[NB];
__device__ float g_ret[NB];

__device__ __forceinline__ float softplusf(float x) {
    return (x > 20.f) ? x : log1pf(expf(x));
}

__device__ __forceinline__ float fast_tanh(float x) {
    float y;
    asm("tanh.approx.f32 %0, %1;" : "=f"(y) : "f"(x));
    return y;
}

// sin(pi*t), cos(pi*t) for t in [-1,1] WITHOUT MUFU sin/cos and WITHOUT F2I/I2F.
// Two reflection folds bring the argument to r = pi*d, d in [0, 0.25]:
//   sin(pi*a) = sin(pi*(1-a)); cos(pi*a) = -cos(pi*(1-a))    [a > 0.5]
//   sin(pi*b) = cos(pi*(0.5-b)); cos(pi*b) = sin(pi*(0.5-b)) [b > 0.25]
// Degree-7/6 kernels on [0, pi/4]: abs err ~2e-7.
__device__ __forceinline__ void sincospi_t(float t, float& s, float& c) {
    float at = fabsf(t);
    bool f1 = at > 0.5f;
    float b = f1 ? (1.0f - at) : at;        // [0, 0.5]
    bool f2 = b > 0.25f;
    float d = f2 ? (0.5f - b) : b;          // [0, 0.25]
    float r = d * PIF;                      // [0, pi/4]
    float w = r * r;
    float ps = fmaf(w, -1.9515296e-4f, 8.3321609e-3f);
    ps = fmaf(w, ps, -1.6666655e-1f);
    float sinr = fmaf(r * w, ps, r);
    float pc = fmaf(w, 2.4433157e-5f, -1.3887316e-3f);
    pc = fmaf(w, pc, 4.1666642e-2f);
    float cosr = fmaf(w * w, pc, fmaf(-0.5f, w, 1.0f));
    float sb = f2 ? cosr : sinr;            // sin(pi*b) >= 0
    float cb = f2 ? sinr : cosr;            // cos(pi*b)
    float ca = f1 ? -cb : cb;               // cos(pi*|t|)
    s = copysignf(sb, t);                   // sin(pi*t)
    c = ca;                                 // cos(pi*t) (even)
}

#define CP_ASYNC16(dst, src) \
    asm volatile("cp.async.cg.shared.global [%0], [%1], 16;" :: "r"(dst), "l"(src))
#define CP_COMMIT() asm volatile("cp.async.commit_group;" ::: "memory")
#define CP_WAIT2()  asm volatile("cp.async.wait_group 2;" ::: "memory")
#define CP_WAIT1()  asm volatile("cp.async.wait_group 1;" ::: "memory")

#define LDSM4(r0, r1, r2, r3, addr) \
    asm volatile("ldmatrix.sync.aligned.m8n8.x4.shared.b16 {%0,%1,%2,%3}, [%4];" \
                 : "=r"(r0), "=r"(r1), "=r"(r2), "=r"(r3) : "r"(addr))

__device__ __forceinline__ uint32_t smem_u32(const void* p) {
    uint32_t a;
    asm("{ .reg .u64 t; cvta.to.shared.u64 t, %1; cvt.u32.u64 %0, t; }" : "=r"(a) : "l"(p));
    return a;
}

// ---------------- fp32 -> fp16 conversions -------------------------------------------
__global__ void cvt3_f2h(const float* __restrict__ s0, const float* __restrict__ s1,
                         const float* __restrict__ s2,
                         __half* __restrict__ d0, __half* __restrict__ d1,
                         __half* __restrict__ d2)
{
    const float* s = (blockIdx.y == 0) ? s0 : (blockIdx.y == 1) ? s1 : s2;
    __half* d = (blockIdx.y == 0) ? d0 : (blockIdx.y == 1) ? d1 : d2;
    const int i = (blockIdx.x * blockDim.x + threadIdx.x) * 8;
    float4 a = *(const float4*)&s[i];
    float4 b = *(const float4*)&s[i + 4];
    __half2 h0 = __floats2half2_rn(a.x, a.y);
    __half2 h1 = __floats2half2_rn(a.z, a.w);
    __half2 h2 = __floats2half2_rn(b.x, b.y);
    __half2 h3 = __floats2half2_rn(b.z, b.w);
    uint4 o;
    o.x = *(uint32_t*)&h0; o.y = *(uint32_t*)&h1;
    o.z = *(uint32_t*)&h2; o.w = *(uint32_t*)&h3;
    *(uint4*)&d[i] = o;
}

__global__ void cvt_f2h(const float* __restrict__ src, __half* __restrict__ dst, int n)
{
    const int i = (blockIdx.x * blockDim.x + threadIdx.x) * 8;
    if (i >= n) return;
    float4 a = *(const float4*)&src[i];
    float4 b = *(const float4*)&src[i + 4];
    __half2 h0 = __floats2half2_rn(a.x, a.y);
    __half2 h1 = __floats2half2_rn(a.z, a.w);
    __half2 h2 = __floats2half2_rn(b.x, b.y);
    __half2 h3 = __floats2half2_rn(b.z, b.w);
    uint4 o;
    o.x = *(uint32_t*)&h0; o.y = *(uint32_t*)&h1;
    o.z = *(uint32_t*)&h2; o.w = *(uint32_t*)&h3;
    *(uint4*)&dst[i] = o;
}

// ---------------- FP16 tensor-core NT GEMM (m16n8k16 + ldmatrix, 2 CTA/SM) -----------
// (R9 baseline: 3-stage cp.async, 2 syncs/iter, lean epilogue)
#define SMS 20
#define KDIM 512
#define KT 32
#define NKT (KDIM / KT)            // 16
#define SA_WORDS (128 * SMS)       // 2560
#define STG_WORDS (2 * SA_WORDS)   // 5120
#define STG_BYTES (STG_WORDS * 4)
#define GEMM_SMEM_BYTES (3 * STG_BYTES)   // 61440

__global__ __launch_bounds__(256, 2)
void gemm_h(const __half* __restrict__ A0, const __half* __restrict__ A1,
            const __half* __restrict__ A2,
            const __half* __restrict__ W, const float* __restrict__ bias,
            const float* __restrict__ R0, const float* __restrict__ R1,
            const float* __restrict__ R2,
            float* __restrict__ C0, float* __restrict__ C1, float* __restrict__ C2,
            __half* __restrict__ Ch0, __half* __restrict__ Ch1, __half* __restrict__ Ch2,
            int N, int mode)
{
    extern __shared__ __align__(16) uint32_t smem[];
    const int tid = threadIdx.x, wid = tid >> 5, lane = tid & 31;
    const int g = lane >> 2, tg = lane & 3;
    const int z = blockIdx.z;
    const __half* A = (z == 0) ? A0 : (z == 1) ? A1 : A2;
    const float*  R = (z == 0) ? R0 : (z == 1) ? R1 : R2;
    float*        C = (z == 0) ? C0 : (z == 1) ? C1 : C2;
    __half*      Ch = (z == 0) ? Ch0 : (z == 1) ? Ch1 : Ch2;
    const int m0 = blockIdx.y * 128;
    const int n0 = blockIdx.x * 128;
    const int moff = (wid & 3) * 32;
    const int noff = (wid >> 2) * 64;
    const __half* Ag = A + (size_t)m0 * KDIM;
    const __half* Bg = W + (size_t)n0 * KDIM;

    const uint32_t sbase = smem_u32(smem);

    const int lrow8 = ((lane >> 3) & 1) * 8 + (lane & 7);
    const int lk4   = (lane >> 4) * 4;
    uint32_t aoff[2], boff[4];
    #pragma unroll
    for (int mt = 0; mt < 2; mt++)
        aoff[mt] = ((moff + mt * 16 + lrow8) * SMS + lk4) * 4;
    #pragma unroll
    for (int ntp = 0; ntp < 4; ntp++)
        boff[ntp] = ((noff + ntp * 16 + lrow8) * SMS + lk4) * 4;

    float acc[2][8][4];
    #pragma unroll
    for (int mt = 0; mt < 2; mt++)
        #pragma unroll
        for (int nt = 0; nt < 8; nt++)
            #pragma unroll
            for (int q = 0; q < 4; q++) acc[mt][nt][q] = 0.f;

    #define FILL_STAGE(stg, k0)                                                      \
    do {                                                                             \
        const uint32_t wA = sbase + (stg) * STG_BYTES;                               \
        const uint32_t wB = wA + SA_WORDS * 4;                                       \
        _Pragma("unroll")                                                            \
        for (int p = 0; p < 2; p++) {                                                \
            const int c = tid + 256 * p;                                             \
            const int row = c >> 2;                                                  \
            CP_ASYNC16(wA + (row * SMS + (c & 3) * 4) * 4,                           \
                       &Ag[(size_t)row * KDIM + (k0) + (c & 3) * 8]);                \
            CP_ASYNC16(wB + (row * SMS + (c & 3) * 4) * 4,                           \
                       &Bg[(size_t)row * KDIM + (k0) + (c & 3) * 8]);                \
        }                                                                            \
    } while (0)

    FILL_STAGE(0, 0);  CP_COMMIT();
    FILL_STAGE(1, KT); CP_COMMIT();
    CP_WAIT1();
    __syncthreads();

    for (int t = 0; t < NKT; t++) {
        if (t + 2 < NKT) { FILL_STAGE((t + 2) % 3, (t + 2) * KT); }
        CP_COMMIT();
        CP_WAIT2();
        __syncthreads();

        const uint32_t Ab = sbase + (t % 3) * STG_BYTES;
        const uint32_t Bb = Ab + SA_WORDS * 4;

        #pragma unroll
        for (int ks = 0; ks < 2; ks++) {
            const uint32_t kb4 = ks * 32;
            uint32_t af[2][4], bf[8][2];
            #pragma unroll
            for (int mt = 0; mt < 2; mt++)
                LDSM4(af[mt][0], af[mt][1], af[mt][2], af[mt][3], Ab + aoff[mt] + kb4);
            #pragma unroll
            for (int ntp = 0; ntp < 4; ntp++)
                LDSM4(bf[2*ntp][0], bf[2*ntp+1][0], bf[2*ntp][1], bf[2*ntp+1][1],
                      Bb + boff[ntp] + kb4);
            #pragma unroll
            for (int mt = 0; mt < 2; mt++)
                #pragma unroll
                for (int nt = 0; nt < 8; nt++) {
                    asm volatile(
                        "mma.sync.aligned.m16n8k16.row.col.f32.f16.f16.f32 "
                        "{%0,%1,%2,%3}, {%4,%5,%6,%7}, {%8,%9}, {%0,%1,%2,%3};"
                        : "+f"(acc[mt][nt][0]), "+f"(acc[mt][nt][1]),
                          "+f"(acc[mt][nt][2]), "+f"(acc[mt][nt][3])
                        : "r"(af[mt][0]), "r"(af[mt][1]), "r"(af[mt][2]), "r"(af[mt][3]),
                          "r"(bf[nt][0]), "r"(bf[nt][1]));
                }
        }
        __syncthreads();
    }

    // ---- epilogue ----
    #pragma unroll
    for (int mt = 0; mt < 2; mt++) {
        #pragma unroll
        for (int nt = 0; nt < 8; nt++) {
            const int n = n0 + noff + nt * 8 + 2 * tg;
            const int ra = m0 + moff + mt * 16 + g;
            const int rb = ra + 8;
            float bx = bias[n], by = bias[n + 1];
            float2 v0 = make_float2(acc[mt][nt][0] + bx, acc[mt][nt][1] + by);
            float2 v1 = make_float2(acc[mt][nt][2] + bx, acc[mt][nt][3] + by);
            if (mode & 1) {
                v0.x = fmaxf(v0.x, 0.f); v0.y = fmaxf(v0.y, 0.f);
                v1.x = fmaxf(v1.x, 0.f); v1.y = fmaxf(v1.y, 0.f);
            }
            if (mode & 2) {
                float2 r0v = *(const float2*)&R[(size_t)ra * N + n];
                float2 r1v = *(const float2*)&R[(size_t)rb * N + n];
                v0.x += r0v.x; v0.y += r0v.y;
                v1.x += r1v.x; v1.y += r1v.y;
            }
            if (mode & 4) {
                *(float2*)&C[(size_t)ra * N + n] = v0;
                *(float2*)&C[(size_t)rb * N + n] = v1;
            }
            if (mode & 8) {
                __half2 h0 = __floats2half2_rn(v0.x, v0.y);
                __half2 h1 = __floats2half2_rn(v1.x, v1.y);
                *(__half2*)&Ch[(size_t)ra * N + n] = h0;
                *(__half2*)&Ch[(size_t)rb * N + n] = h1;
            }
        }
    }
}

// ---------------- three N=1 GEMVs on fp16 E: re_h, rr_r, re_t ------------------------
__global__ void gemv3h(const __half* __restrict__ Eh, const __half* __restrict__ Er,
                       const __half* __restrict__ Et,
                       const float* __restrict__ Wre, const float* __restrict__ bre,
                       const float* __restrict__ Wrr, const float* __restrict__ brr,
                       float* __restrict__ reh, float* __restrict__ rrr, float* __restrict__ ret)
{
    const int warp = (blockIdx.x * blockDim.x + threadIdx.x) >> 5;
    const int lane = threadIdx.x & 31;
    if (warp >= NB) return;
    const __half* eh = Eh + (size_t)warp * HD;
    const __half* er = Er + (size_t)warp * HD;
    const __half* et = Et + (size_t)warp * HD;
    float s1 = 0.f, s2 = 0.f, s3 = 0.f;
    #pragma unroll
    for (int k = lane * 8; k < HD; k += 256) {
        uint4 a = *(const uint4*)&eh[k];
        uint4 b = *(const uint4*)&er[k];
        uint4 c = *(const uint4*)&et[k];
        #pragma unroll
        for (int j = 0; j < 4; j++) {
            float2 ea = __half22float2(*(const __half2*)((const uint32_t*)&a + j));
            float2 eb = __half22float2(*(const __half2*)((const uint32_t*)&b + j));
            float2 ec = __half22float2(*(const __half2*)((const uint32_t*)&c + j));
            float2 wre = *(const float2*)&Wre[k + 2 * j];
            float2 wrr = *(const float2*)&Wrr[k + 2 * j];
            s1 = fmaf(ea.x, wre.x, fmaf(ea.y, wre.y, s1));
            s2 = fmaf(eb.x, wrr.x, fmaf(eb.y, wrr.y, s2));
            s3 = fmaf(ec.x, wre.x, fmaf(ec.y, wre.y, s3));
        }
    }
    #pragma unroll
    for (int o = 16; o > 0; o >>= 1) {
        s1 += __shfl_down_sync(0xffffffffu, s1, o);
        s2 += __shfl_down_sync(0xffffffffu, s2, o);
        s3 += __shfl_down_sync(0xffffffffu, s3, o);
    }
    if (lane == 0) {
        reh[warp] = s1 + bre[0];
        rrr[warp] = s2 + brr[0];
        ret[warp] = s3 + bre[0];
    }
}

// ---- theta transpose + sincos: scT[c][b] = (sin, cos)(pi * tanh(TH[b][c])) ----------
__global__ void transpose_sc(const float* __restrict__ in, float2* __restrict__ out)
{
    __shared__ float tile[32][33];
    const int tx = threadIdx.x, ty = threadIdx.y;
    const int x = blockIdx.x * 32 + tx;
    const int y0 = blockIdx.y * 32;
    #pragma unroll
    for (int j = ty; j < 32; j += 8)
        tile[j][tx] = in[(size_t)(y0 + j) * NP + x];
    __syncthreads();
    const int c0 = blockIdx.x * 32;
    #pragma unroll
    for (int j = ty; j < 32; j += 8) {
        float t = fast_tanh(tile[tx][j]);
        float s, c;
        sincospi_t(t, s, c);
        out[(size_t)(c0 + j) * NB + y0 + tx] = make_float2(s, c);
    }
}

// ---------------- fused l2-norm + transpose: outT[c, b] = in[b, c]/||in[b,:]|| --------
__global__ __launch_bounds__(256)
void transnorm(const float* __restrict__ in, float* __restrict__ outT)
{
    __shared__ float tile[32][DV + 1];
    __shared__ float rnorm[32];
    const int tid = threadIdx.x, wid = tid >> 5, lane = tid & 31;
    const int y0 = blockIdx.x * 32;

    #pragma unroll 4
    for (int i = 0; i < 32; i++)
        tile[i][tid] = in[(size_t)(y0 + i) * DV + tid];
    __syncthreads();

    #pragma unroll
    for (int rr = 0; rr < 4; rr++) {
        const int row = wid * 4 + rr;
        float s = 0.f;
        #pragma unroll
        for (int c = lane; c < DV; c += 32) { float v = tile[row][c]; s = fmaf(v, v, s); }
        #pragma unroll
        for (int o = 16; o > 0; o >>= 1) s += __shfl_down_sync(0xffffffffu, s, o);
        if (lane == 0) rnorm[row] = 1.f / (sqrtf(s) + EPSF);
    }
    __syncthreads();

    #pragma unroll 4
    for (int i = 0; i < 32; i++) {
        const int idx = tid + 256 * i;
        const int c = idx >> 5, bl = idx & 31;
        outT[(size_t)c * NB + y0 + bl] = tile[bl][c] * rnorm[bl];
    }
}

// ---------------- fused rotation + slerp + score (no MUFU in loops) -------------------
__global__ void rot_score(
    const float* __restrict__ uhT, const float* __restrict__ utT,
    const float2* __restrict__ scT, float* __restrict__ urT,
    const float* __restrict__ sim,
    const float* __restrict__ reh, const float* __restrict__ rrr, const float* __restrict__ ret,
    const float* __restrict__ ga_rho, const float* __restrict__ gb_rho,
    const float* __restrict__ ga_phi, const float* __restrict__ gb_phi,
    float* __restrict__ out)
{
    const int b = blockIdx.x * blockDim.x + threadIdx.x;
    if (b >= NB) return;

    float cur = uhT[b];
    float u0w = 0.f;
    #pragma unroll 4
    for (int i = 0; i < 255; i++) {
        float2 sc = scT[(size_t)i * NB + b];
        float nxt = uhT[(size_t)(i + 1) * NB + b];
        float wi = sc.y * cur - sc.x * nxt;
        urT[(size_t)i * NB + b] = wi;
        if (i == 0) u0w = wi;
        cur = sc.x * cur + sc.y * nxt;
    }
    {
        float2 sc = scT[(size_t)255 * NB + b];
        float w255 = sc.y * cur - sc.x * u0w;
        float w0   = sc.x * cur + sc.y * u0w;
        urT[(size_t)255 * NB + b] = w255;
        urT[b] = w0;
    }

    float dhr = 0.f, dht = 0.f, drt = 0.f, ssq = 0.f;
    const float uh0 = uhT[b], ut0 = utT[b];
    cur = urT[b];
    float w0sav = 0.f;
    #pragma unroll 4
    for (int i = 0; i < 255; i++) {
        float2 sc = scT[(size_t)(256 + i) * NB + b];
        float nxt = urT[(size_t)(i + 1) * NB + b];
        float wi = sc.y * cur - sc.x * nxt;
        cur = sc.x * cur + sc.y * nxt;
        if (i == 0) {
            w0sav = wi;
        } else {
            float uh = uhT[(size_t)i * NB + b];
            float ut = utT[(size_t)i * NB + b];
            ssq += wi * wi; dhr += wi * uh; drt += wi * ut; dht += uh * ut;
        }
    }
    float w255f, w0f;
    {
        float2 sc = scT[(size_t)511 * NB + b];
        w255f = sc.y * cur - sc.x * w0sav;
        w0f   = sc.x * cur + sc.y * w0sav;
    }
    {
        float uh255 = uhT[(size_t)255 * NB + b], ut255 = utT[(size_t)255 * NB + b];
        ssq += w255f * w255f + w0f * w0f;
        dhr += w255f * uh255 + w0f * uh0;
        drt += w255f * ut255 + w0f * ut0;
        dht += uh255 * ut255 + uh0 * ut0;
    }

    float nr = sqrtf(ssq);
    float inv_rot = 1.f / (nr + EPSF);
    float dhr_n = dhr * inv_rot;
    float dotc = fminf(fmaxf(dhr_n, -1.f + EPSF), 1.f - EPSF);
    float omega = acosf(dotc);
    float sin_om = sinf(omega);
    float sv = sim[b];
    float grho = 1.f / (1.f + expf(-(ga_rho[0] * sv + gb_rho[0])));
    float gphi = 1.f / (1.f + expf(-(ga_phi[0] * sv + gb_phi[0])));
    float ca, cb;
    if (omega > DELTAF) {
        float iso = 1.f / (sin_om + EPSF);
        ca = sinf((1.f - gphi) * omega) * iso;
        cb = sinf(gphi * omega) * iso;
    } else {
        ca = 1.f - gphi; cb = gphi;
    }
    float nrn = nr * inv_rot;
    float np2 = ca * ca + cb * cb * nrn * nrn + 2.f * ca * cb * dhr_n;
    float npv = sqrtf(fmaxf(np2, 0.f));
    float inv_np = 1.f / (npv + EPSF);
    float dpt = (ca * dht + cb * drt * inv_rot) * inv_np;

    float rho_h = fminf(softplusf(reh[b]), RHO_MAXF);
    float rho_p = fminf(fmaxf(rho_h + rrr[b] * grho, 0.f), RHO_MAXF);
    float rho_t = fminf(softplusf(ret[b]), RHO_MAXF);
    out[b] = -coshf(rho_p) * coshf(rho_t) + sinhf(rho_p) * sinhf(rho_t) * dpt;
}

// ---------------- launch --------------------------------------------------------------
extern "C" void kernel_launch(void* const* d_in, const int* in_sizes, int n_in,
                              void* d_out, int out_size)
{
    const float* ent  = (const float*)d_in[0];
    const float* rel  = (const float*)d_in[1];
    const float* lab  = (const float*)d_in[2];
    const float* sim  = (const float*)d_in[3];
    const float* Wv   = (const float*)d_in[4];
    const float* bv   = (const float*)d_in[5];
    const float* Wre  = (const float*)d_in[6];
    const float* bre  = (const float*)d_in[7];
    const float* Wrr  = (const float*)d_in[8];
    const float* brr  = (const float*)d_in[9];
    const float* Wt   = (const float*)d_in[10];
    const float* bt   = (const float*)d_in[11];
    const float* ga_rho = (const float*)d_in[12];
    const float* gb_rho = (const float*)d_in[13];
    const float* ga_phi = (const float*)d_in[14];
    const float* gb_phi = (const float*)d_in[15];
    const float* W1   = (const float*)d_in[16];
    const float* b1   = (const float*)d_in[17];
    const float* W2   = (const float*)d_in[18];
    const float* b2   = (const float*)d_in[19];
    float* out = (float*)d_out;

    __half *hEnt, *hRel, *hLab, *hH0, *hH1, *hH2, *hEh, *hEr, *hEt;
    __half *hW1, *hW2, *hWv, *hWt;
    float *Vh, *Vt, *TH, *uhT, *utT, *urT, *reh, *rrr, *ret;
    float2 *scT;
    cudaGetSymbolAddress((void**)&hEnt, g_hEnt);
    cudaGetSymbolAddress((void**)&hRel, g_hRel);
    cudaGetSymbolAddress((void**)&hLab, g_hLab);
    cudaGetSymbolAddress((void**)&hH0,  g_hH0);
    cudaGetSymbolAddress((void**)&hH1,  g_hH1);
    cudaGetSymbolAddress((void**)&hH2,  g_hH2);
    cudaGetSymbolAddress((void**)&hEh,  g_hEh);
    cudaGetSymbolAddress((void**)&hEr,  g_hEr);
    cudaGetSymbolAddress((void**)&hEt,  g_hEt);
    cudaGetSymbolAddress((void**)&hW1,  g_hW1);
    cudaGetSymbolAddress((void**)&hW2,  g_hW2);
    cudaGetSymbolAddress((void**)&hWv,  g_hWv);
    cudaGetSymbolAddress((void**)&hWt,  g_hWt);
    cudaGetSymbolAddress((void**)&Vh,   g_Vh);
    cudaGetSymbolAddress((void**)&Vt,   g_Vt);
    cudaGetSymbolAddress((void**)&TH,   g_TH);
    cudaGetSymbolAddress((void**)&scT,  g_scT);
    cudaGetSymbolAddress((void**)&uhT,  g_uhT);
    cudaGetSymbolAddress((void**)&utT,  g_utT);
    cudaGetSymbolAddress((void**)&urT,  g_urT);
    cudaGetSymbolAddress((void**)&reh,  g_reh);
    cudaGetSymbolAddress((void**)&rrr,  g_rrr);
    cudaGetSymbolAddress((void**)&ret,  g_ret);

    cudaFuncSetAttribute(gemm_h, cudaFuncAttributeMaxDynamicSharedMemorySize,
                         GEMM_SMEM_BYTES);

    // fp32 -> fp16 conversions (inputs batched + weights)
    const int BIG = NB * HD;
    cvt3_f2h<<<dim3(BIG / (256 * 8), 3), 256>>>(ent, rel, lab, hEnt, hRel, hLab);
    cvt_f2h<<<(HD * HD) / (256 * 8), 256>>>(W1, hW1, HD * HD);
    cvt_f2h<<<(HD * HD) / (256 * 8), 256>>>(W2, hW2, HD * HD);
    cvt_f2h<<<(DV * HD) / (256 * 8), 256>>>(Wv, hWv, DV * HD);
    cvt_f2h<<<(NP * HD) / (256 * 8), 256>>>(Wt, hWt, NP * HD);

    const dim3 blk(256);
    // layer 1: hH_z = fp16(relu(X_z @ W1^T + b1))         mode 1|8 = 9
    gemm_h<<<dim3(HD/128, NB/128, 3), blk, GEMM_SMEM_BYTES>>>(
        hEnt, hRel, hLab, hW1, b1, nullptr, nullptr, nullptr,
        nullptr, nullptr, nullptr, hH0, hH1, hH2, HD, 9);
    // layer 2: hE_z = fp16(H_z @ W2^T + b2 + X_z)         mode 2|8 = 10
    gemm_h<<<dim3(HD/128, NB/128, 3), blk, GEMM_SMEM_BYTES>>>(
        hH0, hH1, hH2, hW2, b2, ent, rel, lab,
        nullptr, nullptr, nullptr, hEh, hEr, hEt, HD, 10);
    // Wv projections (fp32 out)                           mode 4
    gemm_h<<<dim3(DV/128, NB/128, 2), blk, GEMM_SMEM_BYTES>>>(
        hEh, hEt, nullptr, hWv, bv, nullptr, nullptr, nullptr,
        Vh, Vt, nullptr, nullptr, nullptr, nullptr, DV, 4);
    // theta logits (fp32 out)                             mode 4
    gemm_h<<<dim3(NP/128, NB/128, 1), blk, GEMM_SMEM_BYTES>>>(
        hEr, nullptr, nullptr, hWt, bt, nullptr, nullptr, nullptr,
        TH, nullptr, nullptr, nullptr, nullptr, nullptr, NP, 4);

    // scalar GEMVs (rho logits / delta_rho) on fp16 E
    gemv3h<<<NB / 8, 256>>>(hEh, hEr, hEt, Wre, bre, Wrr, brr, reh, rrr, ret);

    // transposes: thetas -> (sin, cos) via FMA-pipe sincospi; normalized u vectors
    transpose_sc<<<dim3(NP / 32, NB / 32), dim3(32, 8)>>>(TH, scT);
    transnorm<<<NB / 32, 256>>>(Vh, uhT);
    transnorm<<<NB / 32, 256>>>(Vt, utT);

    // fused Givens sweeps + slerp + hyperbolic score
    rot_score<<<NB / 256, 256>>>(uhT, utT, scT, urT, sim, reh, rrr, ret,
                                 ga_rho, gb_rho, ga_phi, gb_phi, out);
    (void)in_sizes; (void)n_in; (void)out_size;
}

// round 13
// speedup vs baseline: 1.3037x; 1.2906x over previous
#include <cuda_runtime.h>
#include <cuda_fp16.h>
#include <math.h>
#include <stdint.h>

#define NB 32768
#define HD 512
#define DV 256
#define NP 512
#define RHO_MAXF 9.0f
#define DELTAF 0.001f
#define EPSF 1e-8f
#define PIF 3.14159265358979f

// ---------------- scratch (__device__ globals: no allocations allowed) ----------------
__device__ __half g_hEnt[NB*HD];
__device__ __half g_hRel[NB*HD];
__device__ __half g_hLab[NB*HD];
__device__ __half g_hH0[NB*HD];
__device__ __half g_hH1[NB*HD];
__device__ __half g_hH2[NB*HD];
__device__ __half g_hEh[NB*HD];
__device__ __half g_hEr[NB*HD];
__device__ __half g_hEt[NB*HD];
__device__ __half g_hW1[HD*HD];
__device__ __half g_hW2[HD*HD];
__device__ __half g_hWv[DV*HD];
__device__ __half g_hWt[NP*HD];
__device__ float g_Vh[NB*DV];
__device__ float g_Vt[NB*DV];
__device__ float g_TH[NB*NP];
__device__ float g_reh[NB];
__device__ float g_rrr[NB];
__device__ float g_ret[NB];

__device__ __forceinline__ float softplusf(float x) {
    return (x > 20.f) ? x : log1pf(expf(x));
}

__device__ __forceinline__ float fast_tanh(float x) {
    float y;
    asm("tanh.approx.f32 %0, %1;" : "=f"(y) : "f"(x));
    return y;
}

// sin(pi*t), cos(pi*t) for t in [-1,1] on the FMA pipe (no MUFU sin/cos, no F2I).
__device__ __forceinline__ void sincospi_t(float t, float& s, float& c) {
    float at = fabsf(t);
    bool f1 = at > 0.5f;
    float b = f1 ? (1.0f - at) : at;
    bool f2 = b > 0.25f;
    float d = f2 ? (0.5f - b) : b;
    float r = d * PIF;
    float w = r * r;
    float ps = fmaf(w, -1.9515296e-4f, 8.3321609e-3f);
    ps = fmaf(w, ps, -1.6666655e-1f);
    float sinr = fmaf(r * w, ps, r);
    float pc = fmaf(w, 2.4433157e-5f, -1.3887316e-3f);
    pc = fmaf(w, pc, 4.1666642e-2f);
    float cosr = fmaf(w * w, pc, fmaf(-0.5f, w, 1.0f));
    float sb = f2 ? cosr : sinr;
    float cb = f2 ? sinr : cosr;
    float ca = f1 ? -cb : cb;
    s = copysignf(sb, t);
    c = ca;
}

#define CP_ASYNC16(dst, src) \
    asm volatile("cp.async.cg.shared.global [%0], [%1], 16;" :: "r"(dst), "l"(src))
#define CP_COMMIT() asm volatile("cp.async.commit_group;" ::: "memory")
#define CP_WAIT2()  asm volatile("cp.async.wait_group 2;" ::: "memory")
#define CP_WAIT1()  asm volatile("cp.async.wait_group 1;" ::: "memory")

#define LDSM4(r0, r1, r2, r3, addr) \
    asm volatile("ldmatrix.sync.aligned.m8n8.x4.shared.b16 {%0,%1,%2,%3}, [%4];" \
                 : "=r"(r0), "=r"(r1), "=r"(r2), "=r"(r3) : "r"(addr))

__device__ __forceinline__ uint32_t smem_u32(const void* p) {
    uint32_t a;
    asm("{ .reg .u64 t; cvta.to.shared.u64 t, %1; cvt.u32.u64 %0, t; }" : "=r"(a) : "l"(p));
    return a;
}

// ---------------- fp32 -> fp16 conversions -------------------------------------------
__global__ void cvt3_f2h(const float* __restrict__ s0, const float* __restrict__ s1,
                         const float* __restrict__ s2,
                         __half* __restrict__ d0, __half* __restrict__ d1,
                         __half* __restrict__ d2)
{
    const float* s = (blockIdx.y == 0) ? s0 : (blockIdx.y == 1) ? s1 : s2;
    __half* d = (blockIdx.y == 0) ? d0 : (blockIdx.y == 1) ? d1 : d2;
    const int i = (blockIdx.x * blockDim.x + threadIdx.x) * 8;
    float4 a = *(const float4*)&s[i];
    float4 b = *(const float4*)&s[i + 4];
    __half2 h0 = __floats2half2_rn(a.x, a.y);
    __half2 h1 = __floats2half2_rn(a.z, a.w);
    __half2 h2 = __floats2half2_rn(b.x, b.y);
    __half2 h3 = __floats2half2_rn(b.z, b.w);
    uint4 o;
    o.x = *(uint32_t*)&h0; o.y = *(uint32_t*)&h1;
    o.z = *(uint32_t*)&h2; o.w = *(uint32_t*)&h3;
    *(uint4*)&d[i] = o;
}

__global__ void cvt_f2h(const float* __restrict__ src, __half* __restrict__ dst, int n)
{
    const int i = (blockIdx.x * blockDim.x + threadIdx.x) * 8;
    if (i >= n) return;
    float4 a = *(const float4*)&src[i];
    float4 b = *(const float4*)&src[i + 4];
    __half2 h0 = __floats2half2_rn(a.x, a.y);
    __half2 h1 = __floats2half2_rn(a.z, a.w);
    __half2 h2 = __floats2half2_rn(b.x, b.y);
    __half2 h3 = __floats2half2_rn(b.z, b.w);
    uint4 o;
    o.x = *(uint32_t*)&h0; o.y = *(uint32_t*)&h1;
    o.z = *(uint32_t*)&h2; o.w = *(uint32_t*)&h3;
    *(uint4*)&dst[i] = o;
}

// ---------------- FP16 tensor-core NT GEMM (R9 baseline) -----------------------------
#define SMS 20
#define KDIM 512
#define KT 32
#define NKT (KDIM / KT)
#define SA_WORDS (128 * SMS)
#define STG_WORDS (2 * SA_WORDS)
#define STG_BYTES (STG_WORDS * 4)
#define GEMM_SMEM_BYTES (3 * STG_BYTES)

__global__ __launch_bounds__(256, 2)
void gemm_h(const __half* __restrict__ A0, const __half* __restrict__ A1,
            const __half* __restrict__ A2,
            const __half* __restrict__ W, const float* __restrict__ bias,
            const float* __restrict__ R0, const float* __restrict__ R1,
            const float* __restrict__ R2,
            float* __restrict__ C0, float* __restrict__ C1, float* __restrict__ C2,
            __half* __restrict__ Ch0, __half* __restrict__ Ch1, __half* __restrict__ Ch2,
            int N, int mode)
{
    extern __shared__ __align__(16) uint32_t smem[];
    const int tid = threadIdx.x, wid = tid >> 5, lane = tid & 31;
    const int g = lane >> 2, tg = lane & 3;
    const int z = blockIdx.z;
    const __half* A = (z == 0) ? A0 : (z == 1) ? A1 : A2;
    const float*  R = (z == 0) ? R0 : (z == 1) ? R1 : R2;
    float*        C = (z == 0) ? C0 : (z == 1) ? C1 : C2;
    __half*      Ch = (z == 0) ? Ch0 : (z == 1) ? Ch1 : Ch2;
    const int m0 = blockIdx.y * 128;
    const int n0 = blockIdx.x * 128;
    const int moff = (wid & 3) * 32;
    const int noff = (wid >> 2) * 64;
    const __half* Ag = A + (size_t)m0 * KDIM;
    const __half* Bg = W + (size_t)n0 * KDIM;

    const uint32_t sbase = smem_u32(smem);

    const int lrow8 = ((lane >> 3) & 1) * 8 + (lane & 7);
    const int lk4   = (lane >> 4) * 4;
    uint32_t aoff[2], boff[4];
    #pragma unroll
    for (int mt = 0; mt < 2; mt++)
        aoff[mt] = ((moff + mt * 16 + lrow8) * SMS + lk4) * 4;
    #pragma unroll
    for (int ntp = 0; ntp < 4; ntp++)
        boff[ntp] = ((noff + ntp * 16 + lrow8) * SMS + lk4) * 4;

    float acc[2][8][4];
    #pragma unroll
    for (int mt = 0; mt < 2; mt++)
        #pragma unroll
        for (int nt = 0; nt < 8; nt++)
            #pragma unroll
            for (int q = 0; q < 4; q++) acc[mt][nt][q] = 0.f;

    #define FILL_STAGE(stg, k0)                                                      \
    do {                                                                             \
        const uint32_t wA = sbase + (stg) * STG_BYTES;                               \
        const uint32_t wB = wA + SA_WORDS * 4;                                       \
        _Pragma("unroll")                                                            \
        for (int p = 0; p < 2; p++) {                                                \
            const int c = tid + 256 * p;                                             \
            const int row = c >> 2;                                                  \
            CP_ASYNC16(wA + (row * SMS + (c & 3) * 4) * 4,                           \
                       &Ag[(size_t)row * KDIM + (k0) + (c & 3) * 8]);                \
            CP_ASYNC16(wB + (row * SMS + (c & 3) * 4) * 4,                           \
                       &Bg[(size_t)row * KDIM + (k0) + (c & 3) * 8]);                \
        }                                                                            \
    } while (0)

    FILL_STAGE(0, 0);  CP_COMMIT();
    FILL_STAGE(1, KT); CP_COMMIT();
    CP_WAIT1();
    __syncthreads();

    for (int t = 0; t < NKT; t++) {
        if (t + 2 < NKT) { FILL_STAGE((t + 2) % 3, (t + 2) * KT); }
        CP_COMMIT();
        CP_WAIT2();
        __syncthreads();

        const uint32_t Ab = sbase + (t % 3) * STG_BYTES;
        const uint32_t Bb = Ab + SA_WORDS * 4;

        #pragma unroll
        for (int ks = 0; ks < 2; ks++) {
            const uint32_t kb4 = ks * 32;
            uint32_t af[2][4], bf[8][2];
            #pragma unroll
            for (int mt = 0; mt < 2; mt++)
                LDSM4(af[mt][0], af[mt][1], af[mt][2], af[mt][3], Ab + aoff[mt] + kb4);
            #pragma unroll
            for (int ntp = 0; ntp < 4; ntp++)
                LDSM4(bf[2*ntp][0], bf[2*ntp+1][0], bf[2*ntp][1], bf[2*ntp+1][1],
                      Bb + boff[ntp] + kb4);
            #pragma unroll
            for (int mt = 0; mt < 2; mt++)
                #pragma unroll
                for (int nt = 0; nt < 8; nt++) {
                    asm volatile(
                        "mma.sync.aligned.m16n8k16.row.col.f32.f16.f16.f32 "
                        "{%0,%1,%2,%3}, {%4,%5,%6,%7}, {%8,%9}, {%0,%1,%2,%3};"
                        : "+f"(acc[mt][nt][0]), "+f"(acc[mt][nt][1]),
                          "+f"(acc[mt][nt][2]), "+f"(acc[mt][nt][3])
                        : "r"(af[mt][0]), "r"(af[mt][1]), "r"(af[mt][2]), "r"(af[mt][3]),
                          "r"(bf[nt][0]), "r"(bf[nt][1]));
                }
        }
        __syncthreads();
    }

    #pragma unroll
    for (int mt = 0; mt < 2; mt++) {
        #pragma unroll
        for (int nt = 0; nt < 8; nt++) {
            const int n = n0 + noff + nt * 8 + 2 * tg;
            const int ra = m0 + moff + mt * 16 + g;
            const int rb = ra + 8;
            float bx = bias[n], by = bias[n + 1];
            float2 v0 = make_float2(acc[mt][nt][0] + bx, acc[mt][nt][1] + by);
            float2 v1 = make_float2(acc[mt][nt][2] + bx, acc[mt][nt][3] + by);
            if (mode & 1) {
                v0.x = fmaxf(v0.x, 0.f); v0.y = fmaxf(v0.y, 0.f);
                v1.x = fmaxf(v1.x, 0.f); v1.y = fmaxf(v1.y, 0.f);
            }
            if (mode & 2) {
                float2 r0v = *(const float2*)&R[(size_t)ra * N + n];
                float2 r1v = *(const float2*)&R[(size_t)rb * N + n];
                v0.x += r0v.x; v0.y += r0v.y;
                v1.x += r1v.x; v1.y += r1v.y;
            }
            if (mode & 4) {
                *(float2*)&C[(size_t)ra * N + n] = v0;
                *(float2*)&C[(size_t)rb * N + n] = v1;
            }
            if (mode & 8) {
                __half2 h0 = __floats2half2_rn(v0.x, v0.y);
                __half2 h1 = __floats2half2_rn(v1.x, v1.y);
                *(__half2*)&Ch[(size_t)ra * N + n] = h0;
                *(__half2*)&Ch[(size_t)rb * N + n] = h1;
            }
        }
    }
}

// ---------------- three N=1 GEMVs on fp16 E ------------------------------------------
__global__ void gemv3h(const __half* __restrict__ Eh, const __half* __restrict__ Er,
                       const __half* __restrict__ Et,
                       const float* __restrict__ Wre, const float* __restrict__ bre,
                       const float* __restrict__ Wrr, const float* __restrict__ brr,
                       float* __restrict__ reh, float* __restrict__ rrr, float* __restrict__ ret)
{
    const int warp = (blockIdx.x * blockDim.x + threadIdx.x) >> 5;
    const int lane = threadIdx.x & 31;
    if (warp >= NB) return;
    const __half* eh = Eh + (size_t)warp * HD;
    const __half* er = Er + (size_t)warp * HD;
    const __half* et = Et + (size_t)warp * HD;
    float s1 = 0.f, s2 = 0.f, s3 = 0.f;
    #pragma unroll
    for (int k = lane * 8; k < HD; k += 256) {
        uint4 a = *(const uint4*)&eh[k];
        uint4 b = *(const uint4*)&er[k];
        uint4 c = *(const uint4*)&et[k];
        #pragma unroll
        for (int j = 0; j < 4; j++) {
            float2 ea = __half22float2(*(const __half2*)((const uint32_t*)&a + j));
            float2 eb = __half22float2(*(const __half2*)((const uint32_t*)&b + j));
            float2 ec = __half22float2(*(const __half2*)((const uint32_t*)&c + j));
            float2 wre = *(const float2*)&Wre[k + 2 * j];
            float2 wrr = *(const float2*)&Wrr[k + 2 * j];
            s1 = fmaf(ea.x, wre.x, fmaf(ea.y, wre.y, s1));
            s2 = fmaf(eb.x, wrr.x, fmaf(eb.y, wrr.y, s2));
            s3 = fmaf(ec.x, wre.x, fmaf(ec.y, wre.y, s3));
        }
    }
    #pragma unroll
    for (int o = 16; o > 0; o >>= 1) {
        s1 += __shfl_down_sync(0xffffffffu, s1, o);
        s2 += __shfl_down_sync(0xffffffffu, s2, o);
        s3 += __shfl_down_sync(0xffffffffu, s3, o);
    }
    if (lane == 0) {
        reh[warp] = s1 + bre[0];
        rrr[warp] = s2 + brr[0];
        ret[warp] = s3 + bre[0];
    }
}

// ================== warp-per-row fused polar + rotation-scan + score =================
// One warp handles one batch row b. Lane t owns elements/rotations [8t, 8t+7].
// Givens chain cur_{i+1} = s_i*cur_i + c_i*nxt_i parallelized by affine-map scan.
#define FULLM 0xffffffffu

// One rotation pass over array xl[8] (per-lane), using sl/cl; returns outputs in xl.
// nxt for lane31,k=7 is x0pre = c0*x[0] - s0*x[1] (the rotation-0 output, input-computable).
__device__ __forceinline__ void rot_pass(float* xl, const float* sl, const float* cl,
                                         int lane)
{
    // broadcast inputs for wrap + chain start
    float x0 = __shfl_sync(FULLM, xl[0], 0);
    float x1 = __shfl_sync(FULLM, xl[1], 0);
    float s0 = __shfl_sync(FULLM, sl[0], 0);
    float c0 = __shfl_sync(FULLM, cl[0], 0);
    float x0pre = c0 * x0 - s0 * x1;

    float nx[8];
    #pragma unroll
    for (int k = 0; k < 7; k++) nx[k] = xl[k + 1];
    nx[7] = __shfl_down_sync(FULLM, xl[0], 1);
    if (lane == 31) nx[7] = x0pre;

    // local affine map: cur_out = A*cur_in + B
    float A = 1.f, B = 0.f;
    #pragma unroll
    for (int k = 0; k < 8; k++) {
        B = fmaf(sl[k], B, cl[k] * nx[k]);
        A *= sl[k];
    }
    // inclusive Kogge-Stone scan of affine composition (earlier lanes applied first)
    #pragma unroll
    for (int d = 1; d < 32; d <<= 1) {
        float pA = __shfl_up_sync(FULLM, A, d);
        float pB = __shfl_up_sync(FULLM, B, d);
        if (lane >= d) {
            B = fmaf(A, pB, B);
            A *= pA;
        }
    }
    // exclusive
    float eA = __shfl_up_sync(FULLM, A, 1);
    float eB = __shfl_up_sync(FULLM, B, 1);
    if (lane == 0) { eA = 1.f; eB = 0.f; }
    float cur = fmaf(eA, x0, eB);

    // recompute outputs
    float w[8];
    #pragma unroll
    for (int k = 0; k < 8; k++) {
        w[k] = cl[k] * cur - sl[k] * nx[k];
        cur = fmaf(sl[k], cur, cl[k] * nx[k]);
    }
    // rotation 255 (lane 31) also produces final x[0] = its chain output
    float x0fin = __shfl_sync(FULLM, cur, 31);
    #pragma unroll
    for (int k = 0; k < 8; k++) xl[k] = w[k];
    if (lane == 0) xl[0] = x0fin;
}

__global__ __launch_bounds__(256)
void polar_score(const float* __restrict__ Vh, const float* __restrict__ Vt,
                 const float* __restrict__ TH,
                 const float* __restrict__ sim,
                 const float* __restrict__ reh, const float* __restrict__ rrr,
                 const float* __restrict__ ret,
                 const float* __restrict__ ga_rho, const float* __restrict__ gb_rho,
                 const float* __restrict__ ga_phi, const float* __restrict__ gb_phi,
                 float* __restrict__ out)
{
    const int b = (blockIdx.x * blockDim.x + threadIdx.x) >> 5;
    const int lane = threadIdx.x & 31;
    if (b >= NB) return;

    const float* vh = Vh + (size_t)b * DV + lane * 8;
    const float* vt = Vt + (size_t)b * DV + lane * 8;
    const float* th = TH + (size_t)b * NP + lane * 8;

    // ---- load u_h, u_t rows + normalize in registers ----
    float uh[8], ut[8];
    {
        float4 a0 = *(const float4*)&vh[0];
        float4 a1 = *(const float4*)&vh[4];
        uh[0]=a0.x; uh[1]=a0.y; uh[2]=a0.z; uh[3]=a0.w;
        uh[4]=a1.x; uh[5]=a1.y; uh[6]=a1.z; uh[7]=a1.w;
        float4 b0 = *(const float4*)&vt[0];
        float4 b1 = *(const float4*)&vt[4];
        ut[0]=b0.x; ut[1]=b0.y; ut[2]=b0.z; ut[3]=b0.w;
        ut[4]=b1.x; ut[5]=b1.y; ut[6]=b1.z; ut[7]=b1.w;
    }
    float nh = 0.f, nt2 = 0.f;
    #pragma unroll
    for (int k = 0; k < 8; k++) { nh = fmaf(uh[k], uh[k], nh); nt2 = fmaf(ut[k], ut[k], nt2); }
    #pragma unroll
    for (int o = 16; o > 0; o >>= 1) {
        nh  += __shfl_xor_sync(FULLM, nh,  o);
        nt2 += __shfl_xor_sync(FULLM, nt2, o);
    }
    float ih = 1.f / (sqrtf(nh) + EPSF);
    float it = 1.f / (sqrtf(nt2) + EPSF);
    #pragma unroll
    for (int k = 0; k < 8; k++) { uh[k] *= ih; ut[k] *= it; }

    // ---- pass 1: rotations 0..255 on u_h ----
    float sl[8], cl[8];
    {
        float4 t0 = *(const float4*)&th[0];
        float4 t1 = *(const float4*)&th[4];
        float tv[8] = {t0.x, t0.y, t0.z, t0.w, t1.x, t1.y, t1.z, t1.w};
        #pragma unroll
        for (int k = 0; k < 8; k++)
            sincospi_t(fast_tanh(tv[k]), sl[k], cl[k]);
    }
    float w[8];
    #pragma unroll
    for (int k = 0; k < 8; k++) w[k] = uh[k];
    rot_pass(w, sl, cl, lane);

    // ---- pass 2: rotations 256..511 on w ----
    {
        float4 t0 = *(const float4*)&th[256];
        float4 t1 = *(const float4*)&th[260];
        float tv[8] = {t0.x, t0.y, t0.z, t0.w, t1.x, t1.y, t1.z, t1.w};
        #pragma unroll
        for (int k = 0; k < 8; k++)
            sincospi_t(fast_tanh(tv[k]), sl[k], cl[k]);
    }
    rot_pass(w, sl, cl, lane);   // w now holds u_rot (unnormalized)

    // ---- dots ----
    float ssq = 0.f, dhr = 0.f, drt = 0.f, dht = 0.f;
    #pragma unroll
    for (int k = 0; k < 8; k++) {
        ssq = fmaf(w[k], w[k], ssq);
        dhr = fmaf(w[k], uh[k], dhr);
        drt = fmaf(w[k], ut[k], drt);
        dht = fmaf(uh[k], ut[k], dht);
    }
    #pragma unroll
    for (int o = 16; o > 0; o >>= 1) {
        ssq += __shfl_xor_sync(FULLM, ssq, o);
        dhr += __shfl_xor_sync(FULLM, dhr, o);
        drt += __shfl_xor_sync(FULLM, drt, o);
        dht += __shfl_xor_sync(FULLM, dht, o);
    }

    if (lane != 0) return;

    float nr = sqrtf(ssq);
    float inv_rot = 1.f / (nr + EPSF);
    float dhr_n = dhr * inv_rot;
    float dotc = fminf(fmaxf(dhr_n, -1.f + EPSF), 1.f - EPSF);
    float omega = acosf(dotc);
    float sin_om = sinf(omega);
    float sv = sim[b];
    float grho = 1.f / (1.f + expf(-(ga_rho[0] * sv + gb_rho[0])));
    float gphi = 1.f / (1.f + expf(-(ga_phi[0] * sv + gb_phi[0])));
    float ca, cb;
    if (omega > DELTAF) {
        float iso = 1.f / (sin_om + EPSF);
        ca = sinf((1.f - gphi) * omega) * iso;
        cb = sinf(gphi * omega) * iso;
    } else {
        ca = 1.f - gphi; cb = gphi;
    }
    float nrn = nr * inv_rot;
    float np2 = ca * ca + cb * cb * nrn * nrn + 2.f * ca * cb * dhr_n;
    float npv = sqrtf(fmaxf(np2, 0.f));
    float inv_np = 1.f / (npv + EPSF);
    float dpt = (ca * dht + cb * drt * inv_rot) * inv_np;

    float rho_h = fminf(softplusf(reh[b]), RHO_MAXF);
    float rho_p = fminf(fmaxf(rho_h + rrr[b] * grho, 0.f), RHO_MAXF);
    float rho_t = fminf(softplusf(ret[b]), RHO_MAXF);
    out[b] = -coshf(rho_p) * coshf(rho_t) + sinhf(rho_p) * sinhf(rho_t) * dpt;
}

// ---------------- launch --------------------------------------------------------------
extern "C" void kernel_launch(void* const* d_in, const int* in_sizes, int n_in,
                              void* d_out, int out_size)
{
    const float* ent  = (const float*)d_in[0];
    const float* rel  = (const float*)d_in[1];
    const float* lab  = (const float*)d_in[2];
    const float* sim  = (const float*)d_in[3];
    const float* Wv   = (const float*)d_in[4];
    const float* bv   = (const float*)d_in[5];
    const float* Wre  = (const float*)d_in[6];
    const float* bre  = (const float*)d_in[7];
    const float* Wrr  = (const float*)d_in[8];
    const float* brr  = (const float*)d_in[9];
    const float* Wt   = (const float*)d_in[10];
    const float* bt   = (const float*)d_in[11];
    const float* ga_rho = (const float*)d_in[12];
    const float* gb_rho = (const float*)d_in[13];
    const float* ga_phi = (const float*)d_in[14];
    const float* gb_phi = (const float*)d_in[15];
    const float* W1   = (const float*)d_in[16];
    const float* b1   = (const float*)d_in[17];
    const float* W2   = (const float*)d_in[18];
    const float* b2   = (const float*)d_in[19];
    float* out = (float*)d_out;

    __half *hEnt, *hRel, *hLab, *hH0, *hH1, *hH2, *hEh, *hEr, *hEt;
    __half *hW1, *hW2, *hWv, *hWt;
    float *Vh, *Vt, *TH, *reh, *rrr, *ret;
    cudaGetSymbolAddress((void**)&hEnt, g_hEnt);
    cudaGetSymbolAddress((void**)&hRel, g_hRel);
    cudaGetSymbolAddress((void**)&hLab, g_hLab);
    cudaGetSymbolAddress((void**)&hH0,  g_hH0);
    cudaGetSymbolAddress((void**)&hH1,  g_hH1);
    cudaGetSymbolAddress((void**)&hH2,  g_hH2);
    cudaGetSymbolAddress((void**)&hEh,  g_hEh);
    cudaGetSymbolAddress((void**)&hEr,  g_hEr);
    cudaGetSymbolAddress((void**)&hEt,  g_hEt);
    cudaGetSymbolAddress((void**)&hW1,  g_hW1);
    cudaGetSymbolAddress((void**)&hW2,  g_hW2);
    cudaGetSymbolAddress((void**)&hWv,  g_hWv);
    cudaGetSymbolAddress((void**)&hWt,  g_hWt);
    cudaGetSymbolAddress((void**)&Vh,   g_Vh);
    cudaGetSymbolAddress((void**)&Vt,   g_Vt);
    cudaGetSymbolAddress((void**)&TH,   g_TH);
    cudaGetSymbolAddress((void**)&reh,  g_reh);
    cudaGetSymbolAddress((void**)&rrr,  g_rrr);
    cudaGetSymbolAddress((void**)&ret,  g_ret);

    cudaFuncSetAttribute(gemm_h, cudaFuncAttributeMaxDynamicSharedMemorySize,
                         GEMM_SMEM_BYTES);

    const int BIG = NB * HD;
    cvt3_f2h<<<dim3(BIG / (256 * 8), 3), 256>>>(ent, rel, lab, hEnt, hRel, hLab);
    cvt_f2h<<<(HD * HD) / (256 * 8), 256>>>(W1, hW1, HD * HD);
    cvt_f2h<<<(HD * HD) / (256 * 8), 256>>>(W2, hW2, HD * HD);
    cvt_f2h<<<(DV * HD) / (256 * 8), 256>>>(Wv, hWv, DV * HD);
    cvt_f2h<<<(NP * HD) / (256 * 8), 256>>>(Wt, hWt, NP * HD);

    const dim3 blk(256);
    gemm_h<<<dim3(HD/128, NB/128, 3), blk, GEMM_SMEM_BYTES>>>(
        hEnt, hRel, hLab, hW1, b1, nullptr, nullptr, nullptr,
        nullptr, nullptr, nullptr, hH0, hH1, hH2, HD, 9);
    gemm_h<<<dim3(HD/128, NB/128, 3), blk, GEMM_SMEM_BYTES>>>(
        hH0, hH1, hH2, hW2, b2, ent, rel, lab,
        nullptr, nullptr, nullptr, hEh, hEr, hEt, HD, 10);
    gemm_h<<<dim3(DV/128, NB/128, 2), blk, GEMM_SMEM_BYTES>>>(
        hEh, hEt, nullptr, hWv, bv, nullptr, nullptr, nullptr,
        Vh, Vt, nullptr, nullptr, nullptr, nullptr, DV, 4);
    gemm_h<<<dim3(NP/128, NB/128, 1), blk, GEMM_SMEM_BYTES>>>(
        hEr, nullptr, nullptr, hWt, bt, nullptr, nullptr, nullptr,
        TH, nullptr, nullptr, nullptr, nullptr, nullptr, NP, 4);

    gemv3h<<<NB / 8, 256>>>(hEh, hEr, hEt, Wre, bre, Wrr, brr, reh, rrr, ret);

    // fused warp-per-row: normalize + 512 Givens rotations (affine scan) + score
    polar_score<<<(NB * 32) / 256, 256>>>(Vh, Vt, TH, sim, reh, rrr, ret,
                                          ga_rho, gb_rho, ga_phi, gb_phi, out);
    (void)in_sizes; (void)n_in; (void)out_size;
}

// round 14
// speedup vs baseline: 1.3222x; 1.0142x over previous
#include <cuda_runtime.h>
#include <cuda_fp16.h>
#include <math.h>
#include <stdint.h>

#define NB 32768
#define HD 512
#define DV 256
#define NP 512
#define RHO_MAXF 9.0f
#define DELTAF 0.001f
#define EPSF 1e-8f
#define PIF 3.14159265358979f

// ---------------- scratch (__device__ globals: no allocations allowed) ----------------
__device__ __half g_hEnt[NB*HD];
__device__ __half g_hRel[NB*HD];
__device__ __half g_hLab[NB*HD];
__device__ __half g_hH0[NB*HD];   // layer-1 hidden; reused as fp16 Vh after layer 2
__device__ __half g_hH1[NB*HD];   // layer-1 hidden; reused as fp16 Vt
__device__ __half g_hH2[NB*HD];   // layer-1 hidden; reused as fp16 TH
__device__ __half g_hEh[NB*HD];
__device__ __half g_hEr[NB*HD];
__device__ __half g_hEt[NB*HD];
__device__ __half g_hW1[HD*HD];
__device__ __half g_hW2[HD*HD];
__device__ __half g_hWv[DV*HD];
__device__ __half g_hWt[NP*HD];
__device__ float g_reh[NB];
__device__ float g_rrr[NB];
__device__ float g_ret[NB];

__device__ __forceinline__ float softplusf(float x) {
    return (x > 20.f) ? x : log1pf(expf(x));
}

__device__ __forceinline__ float fast_tanh(float x) {
    float y;
    asm("tanh.approx.f32 %0, %1;" : "=f"(y) : "f"(x));
    return y;
}

// sin(pi*t), cos(pi*t) for t in [-1,1] on the FMA pipe (no MUFU sin/cos, no F2I).
__device__ __forceinline__ void sincospi_t(float t, float& s, float& c) {
    float at = fabsf(t);
    bool f1 = at > 0.5f;
    float b = f1 ? (1.0f - at) : at;
    bool f2 = b > 0.25f;
    float d = f2 ? (0.5f - b) : b;
    float r = d * PIF;
    float w = r * r;
    float ps = fmaf(w, -1.9515296e-4f, 8.3321609e-3f);
    ps = fmaf(w, ps, -1.6666655e-1f);
    float sinr = fmaf(r * w, ps, r);
    float pc = fmaf(w, 2.4433157e-5f, -1.3887316e-3f);
    pc = fmaf(w, pc, 4.1666642e-2f);
    float cosr = fmaf(w * w, pc, fmaf(-0.5f, w, 1.0f));
    float sb = f2 ? cosr : sinr;
    float cb = f2 ? sinr : cosr;
    float ca = f1 ? -cb : cb;
    s = copysignf(sb, t);
    c = ca;
}

#define CP_ASYNC16(dst, src) \
    asm volatile("cp.async.cg.shared.global [%0], [%1], 16;" :: "r"(dst), "l"(src))
#define CP_COMMIT() asm volatile("cp.async.commit_group;" ::: "memory")
#define CP_WAIT2()  asm volatile("cp.async.wait_group 2;" ::: "memory")
#define CP_WAIT1()  asm volatile("cp.async.wait_group 1;" ::: "memory")

#define LDSM4(r0, r1, r2, r3, addr) \
    asm volatile("ldmatrix.sync.aligned.m8n8.x4.shared.b16 {%0,%1,%2,%3}, [%4];" \
                 : "=r"(r0), "=r"(r1), "=r"(r2), "=r"(r3) : "r"(addr))

__device__ __forceinline__ uint32_t smem_u32(const void* p) {
    uint32_t a;
    asm("{ .reg .u64 t; cvta.to.shared.u64 t, %1; cvt.u32.u64 %0, t; }" : "=r"(a) : "l"(p));
    return a;
}

// ---------------- fp32 -> fp16 conversions -------------------------------------------
__global__ void cvt3_f2h(const float* __restrict__ s0, const float* __restrict__ s1,
                         const float* __restrict__ s2,
                         __half* __restrict__ d0, __half* __restrict__ d1,
                         __half* __restrict__ d2)
{
    const float* s = (blockIdx.y == 0) ? s0 : (blockIdx.y == 1) ? s1 : s2;
    __half* d = (blockIdx.y == 0) ? d0 : (blockIdx.y == 1) ? d1 : d2;
    const int i = (blockIdx.x * blockDim.x + threadIdx.x) * 8;
    float4 a = *(const float4*)&s[i];
    float4 b = *(const float4*)&s[i + 4];
    __half2 h0 = __floats2half2_rn(a.x, a.y);
    __half2 h1 = __floats2half2_rn(a.z, a.w);
    __half2 h2 = __floats2half2_rn(b.x, b.y);
    __half2 h3 = __floats2half2_rn(b.z, b.w);
    uint4 o;
    o.x = *(uint32_t*)&h0; o.y = *(uint32_t*)&h1;
    o.z = *(uint32_t*)&h2; o.w = *(uint32_t*)&h3;
    *(uint4*)&d[i] = o;
}

__global__ void cvt_f2h(const float* __restrict__ src, __half* __restrict__ dst, int n)
{
    const int i = (blockIdx.x * blockDim.x + threadIdx.x) * 8;
    if (i >= n) return;
    float4 a = *(const float4*)&src[i];
    float4 b = *(const float4*)&src[i + 4];
    __half2 h0 = __floats2half2_rn(a.x, a.y);
    __half2 h1 = __floats2half2_rn(a.z, a.w);
    __half2 h2 = __floats2half2_rn(b.x, b.y);
    __half2 h3 = __floats2half2_rn(b.z, b.w);
    uint4 o;
    o.x = *(uint32_t*)&h0; o.y = *(uint32_t*)&h1;
    o.z = *(uint32_t*)&h2; o.w = *(uint32_t*)&h3;
    *(uint4*)&dst[i] = o;
}

// ---------------- FP16 tensor-core NT GEMM (R9 baseline mainloop) --------------------
// mode bits: 1=relu, 2=+residual fp32(R), 16=+residual fp16(R cast), 8=store fp16 Ch
#define SMS 20
#define KDIM 512
#define KT 32
#define NKT (KDIM / KT)
#define SA_WORDS (128 * SMS)
#define STG_WORDS (2 * SA_WORDS)
#define STG_BYTES (STG_WORDS * 4)
#define GEMM_SMEM_BYTES (3 * STG_BYTES)

__global__ __launch_bounds__(256, 2)
void gemm_h(const __half* __restrict__ A0, const __half* __restrict__ A1,
            const __half* __restrict__ A2,
            const __half* __restrict__ W, const float* __restrict__ bias,
            const void* __restrict__ R0, const void* __restrict__ R1,
            const void* __restrict__ R2,
            __half* __restrict__ Ch0, __half* __restrict__ Ch1, __half* __restrict__ Ch2,
            int N, int mode)
{
    extern __shared__ __align__(16) uint32_t smem[];
    const int tid = threadIdx.x, wid = tid >> 5, lane = tid & 31;
    const int g = lane >> 2, tg = lane & 3;
    const int z = blockIdx.z;
    const __half* A = (z == 0) ? A0 : (z == 1) ? A1 : A2;
    const void*   R = (z == 0) ? R0 : (z == 1) ? R1 : R2;
    __half*      Ch = (z == 0) ? Ch0 : (z == 1) ? Ch1 : Ch2;
    const int m0 = blockIdx.y * 128;
    const int n0 = blockIdx.x * 128;
    const int moff = (wid & 3) * 32;
    const int noff = (wid >> 2) * 64;
    const __half* Ag = A + (size_t)m0 * KDIM;
    const __half* Bg = W + (size_t)n0 * KDIM;

    const uint32_t sbase = smem_u32(smem);

    const int lrow8 = ((lane >> 3) & 1) * 8 + (lane & 7);
    const int lk4   = (lane >> 4) * 4;
    uint32_t aoff[2], boff[4];
    #pragma unroll
    for (int mt = 0; mt < 2; mt++)
        aoff[mt] = ((moff + mt * 16 + lrow8) * SMS + lk4) * 4;
    #pragma unroll
    for (int ntp = 0; ntp < 4; ntp++)
        boff[ntp] = ((noff + ntp * 16 + lrow8) * SMS + lk4) * 4;

    float acc[2][8][4];
    #pragma unroll
    for (int mt = 0; mt < 2; mt++)
        #pragma unroll
        for (int nt = 0; nt < 8; nt++)
            #pragma unroll
            for (int q = 0; q < 4; q++) acc[mt][nt][q] = 0.f;

    #define FILL_STAGE(stg, k0)                                                      \
    do {                                                                             \
        const uint32_t wA = sbase + (stg) * STG_BYTES;                               \
        const uint32_t wB = wA + SA_WORDS * 4;                                       \
        _Pragma("unroll")                                                            \
        for (int p = 0; p < 2; p++) {                                                \
            const int c = tid + 256 * p;                                             \
            const int row = c >> 2;                                                  \
            CP_ASYNC16(wA + (row * SMS + (c & 3) * 4) * 4,                           \
                       &Ag[(size_t)row * KDIM + (k0) + (c & 3) * 8]);                \
            CP_ASYNC16(wB + (row * SMS + (c & 3) * 4) * 4,                           \
                       &Bg[(size_t)row * KDIM + (k0) + (c & 3) * 8]);                \
        }                                                                            \
    } while (0)

    FILL_STAGE(0, 0);  CP_COMMIT();
    FILL_STAGE(1, KT); CP_COMMIT();
    CP_WAIT1();
    __syncthreads();

    for (int t = 0; t < NKT; t++) {
        if (t + 2 < NKT) { FILL_STAGE((t + 2) % 3, (t + 2) * KT); }
        CP_COMMIT();
        CP_WAIT2();
        __syncthreads();

        const uint32_t Ab = sbase + (t % 3) * STG_BYTES;
        const uint32_t Bb = Ab + SA_WORDS * 4;

        #pragma unroll
        for (int ks = 0; ks < 2; ks++) {
            const uint32_t kb4 = ks * 32;
            uint32_t af[2][4], bf[8][2];
            #pragma unroll
            for (int mt = 0; mt < 2; mt++)
                LDSM4(af[mt][0], af[mt][1], af[mt][2], af[mt][3], Ab + aoff[mt] + kb4);
            #pragma unroll
            for (int ntp = 0; ntp < 4; ntp++)
                LDSM4(bf[2*ntp][0], bf[2*ntp+1][0], bf[2*ntp][1], bf[2*ntp+1][1],
                      Bb + boff[ntp] + kb4);
            #pragma unroll
            for (int mt = 0; mt < 2; mt++)
                #pragma unroll
                for (int nt = 0; nt < 8; nt++) {
                    asm volatile(
                        "mma.sync.aligned.m16n8k16.row.col.f32.f16.f16.f32 "
                        "{%0,%1,%2,%3}, {%4,%5,%6,%7}, {%8,%9}, {%0,%1,%2,%3};"
                        : "+f"(acc[mt][nt][0]), "+f"(acc[mt][nt][1]),
                          "+f"(acc[mt][nt][2]), "+f"(acc[mt][nt][3])
                        : "r"(af[mt][0]), "r"(af[mt][1]), "r"(af[mt][2]), "r"(af[mt][3]),
                          "r"(bf[nt][0]), "r"(bf[nt][1]));
                }
        }
        __syncthreads();
    }

    // ---- epilogue ----
    #pragma unroll
    for (int mt = 0; mt < 2; mt++) {
        #pragma unroll
        for (int nt = 0; nt < 8; nt++) {
            const int n = n0 + noff + nt * 8 + 2 * tg;
            const int ra = m0 + moff + mt * 16 + g;
            const int rb = ra + 8;
            float bx = bias[n], by = bias[n + 1];
            float2 v0 = make_float2(acc[mt][nt][0] + bx, acc[mt][nt][1] + by);
            float2 v1 = make_float2(acc[mt][nt][2] + bx, acc[mt][nt][3] + by);
            if (mode & 1) {
                v0.x = fmaxf(v0.x, 0.f); v0.y = fmaxf(v0.y, 0.f);
                v1.x = fmaxf(v1.x, 0.f); v1.y = fmaxf(v1.y, 0.f);
            }
            if (mode & 2) {
                const float* Rf = (const float*)R;
                float2 r0v = *(const float2*)&Rf[(size_t)ra * N + n];
                float2 r1v = *(const float2*)&Rf[(size_t)rb * N + n];
                v0.x += r0v.x; v0.y += r0v.y;
                v1.x += r1v.x; v1.y += r1v.y;
            }
            if (mode & 16) {
                const __half* Rh = (const __half*)R;
                float2 r0v = __half22float2(*(const __half2*)&Rh[(size_t)ra * N + n]);
                float2 r1v = __half22float2(*(const __half2*)&Rh[(size_t)rb * N + n]);
                v0.x += r0v.x; v0.y += r0v.y;
                v1.x += r1v.x; v1.y += r1v.y;
            }
            if (mode & 8) {
                __half2 h0 = __floats2half2_rn(v0.x, v0.y);
                __half2 h1 = __floats2half2_rn(v1.x, v1.y);
                *(__half2*)&Ch[(size_t)ra * N + n] = h0;
                *(__half2*)&Ch[(size_t)rb * N + n] = h1;
            }
        }
    }
}

// ---------------- three N=1 GEMVs on fp16 E ------------------------------------------
__global__ void gemv3h(const __half* __restrict__ Eh, const __half* __restrict__ Er,
                       const __half* __restrict__ Et,
                       const float* __restrict__ Wre, const float* __restrict__ bre,
                       const float* __restrict__ Wrr, const float* __restrict__ brr,
                       float* __restrict__ reh, float* __restrict__ rrr, float* __restrict__ ret)
{
    const int warp = (blockIdx.x * blockDim.x + threadIdx.x) >> 5;
    const int lane = threadIdx.x & 31;
    if (warp >= NB) return;
    const __half* eh = Eh + (size_t)warp * HD;
    const __half* er = Er + (size_t)warp * HD;
    const __half* et = Et + (size_t)warp * HD;
    float s1 = 0.f, s2 = 0.f, s3 = 0.f;
    #pragma unroll
    for (int k = lane * 8; k < HD; k += 256) {
        uint4 a = *(const uint4*)&eh[k];
        uint4 b = *(const uint4*)&er[k];
        uint4 c = *(const uint4*)&et[k];
        #pragma unroll
        for (int j = 0; j < 4; j++) {
            float2 ea = __half22float2(*(const __half2*)((const uint32_t*)&a + j));
            float2 eb = __half22float2(*(const __half2*)((const uint32_t*)&b + j));
            float2 ec = __half22float2(*(const __half2*)((const uint32_t*)&c + j));
            float2 wre = *(const float2*)&Wre[k + 2 * j];
            float2 wrr = *(const float2*)&Wrr[k + 2 * j];
            s1 = fmaf(ea.x, wre.x, fmaf(ea.y, wre.y, s1));
            s2 = fmaf(eb.x, wrr.x, fmaf(eb.y, wrr.y, s2));
            s3 = fmaf(ec.x, wre.x, fmaf(ec.y, wre.y, s3));
        }
    }
    #pragma unroll
    for (int o = 16; o > 0; o >>= 1) {
        s1 += __shfl_down_sync(0xffffffffu, s1, o);
        s2 += __shfl_down_sync(0xffffffffu, s2, o);
        s3 += __shfl_down_sync(0xffffffffu, s3, o);
    }
    if (lane == 0) {
        reh[warp] = s1 + bre[0];
        rrr[warp] = s2 + brr[0];
        ret[warp] = s3 + bre[0];
    }
}

// ================== warp-per-row fused polar + rotation-scan + score =================
#define FULLM 0xffffffffu

__device__ __forceinline__ void rot_pass(float* xl, const float* sl, const float* cl,
                                         int lane)
{
    float x0 = __shfl_sync(FULLM, xl[0], 0);
    float x1 = __shfl_sync(FULLM, xl[1], 0);
    float s0 = __shfl_sync(FULLM, sl[0], 0);
    float c0 = __shfl_sync(FULLM, cl[0], 0);
    float x0pre = c0 * x0 - s0 * x1;

    float nx[8];
    #pragma unroll
    for (int k = 0; k < 7; k++) nx[k] = xl[k + 1];
    nx[7] = __shfl_down_sync(FULLM, xl[0], 1);
    if (lane == 31) nx[7] = x0pre;

    float A = 1.f, B = 0.f;
    #pragma unroll
    for (int k = 0; k < 8; k++) {
        B = fmaf(sl[k], B, cl[k] * nx[k]);
        A *= sl[k];
    }
    #pragma unroll
    for (int d = 1; d < 32; d <<= 1) {
        float pA = __shfl_up_sync(FULLM, A, d);
        float pB = __shfl_up_sync(FULLM, B, d);
        if (lane >= d) {
            B = fmaf(A, pB, B);
            A *= pA;
        }
    }
    float eA = __shfl_up_sync(FULLM, A, 1);
    float eB = __shfl_up_sync(FULLM, B, 1);
    if (lane == 0) { eA = 1.f; eB = 0.f; }
    float cur = fmaf(eA, x0, eB);

    float w[8];
    #pragma unroll
    for (int k = 0; k < 8; k++) {
        w[k] = cl[k] * cur - sl[k] * nx[k];
        cur = fmaf(sl[k], cur, cl[k] * nx[k]);
    }
    float x0fin = __shfl_sync(FULLM, cur, 31);
    #pragma unroll
    for (int k = 0; k < 8; k++) xl[k] = w[k];
    if (lane == 0) xl[0] = x0fin;
}

__device__ __forceinline__ void load8h(const __half* p, float* v) {
    uint4 a = *(const uint4*)p;
    const __half2* hp = (const __half2*)&a;
    float2 f0 = __half22float2(hp[0]);
    float2 f1 = __half22float2(hp[1]);
    float2 f2 = __half22float2(hp[2]);
    float2 f3 = __half22float2(hp[3]);
    v[0]=f0.x; v[1]=f0.y; v[2]=f1.x; v[3]=f1.y;
    v[4]=f2.x; v[5]=f2.y; v[6]=f3.x; v[7]=f3.y;
}

__global__ __launch_bounds__(256)
void polar_score(const __half* __restrict__ Vh, const __half* __restrict__ Vt,
                 const __half* __restrict__ TH,
                 const float* __restrict__ sim,
                 const float* __restrict__ reh, const float* __restrict__ rrr,
                 const float* __restrict__ ret,
                 const float* __restrict__ ga_rho, const float* __restrict__ gb_rho,
                 const float* __restrict__ ga_phi, const float* __restrict__ gb_phi,
                 float* __restrict__ out)
{
    const int b = (blockIdx.x * blockDim.x + threadIdx.x) >> 5;
    const int lane = threadIdx.x & 31;
    if (b >= NB) return;

    float uh[8], ut[8];
    load8h(Vh + (size_t)b * DV + lane * 8, uh);
    load8h(Vt + (size_t)b * DV + lane * 8, ut);

    float nh = 0.f, nt2 = 0.f;
    #pragma unroll
    for (int k = 0; k < 8; k++) { nh = fmaf(uh[k], uh[k], nh); nt2 = fmaf(ut[k], ut[k], nt2); }
    #pragma unroll
    for (int o = 16; o > 0; o >>= 1) {
        nh  += __shfl_xor_sync(FULLM, nh,  o);
        nt2 += __shfl_xor_sync(FULLM, nt2, o);
    }
    float ih = 1.f / (sqrtf(nh) + EPSF);
    float it = 1.f / (sqrtf(nt2) + EPSF);
    #pragma unroll
    for (int k = 0; k < 8; k++) { uh[k] *= ih; ut[k] *= it; }

    float sl[8], cl[8], tv[8];
    load8h(TH + (size_t)b * NP + lane * 8, tv);
    #pragma unroll
    for (int k = 0; k < 8; k++)
        sincospi_t(fast_tanh(tv[k]), sl[k], cl[k]);

    float w[8];
    #pragma unroll
    for (int k = 0; k < 8; k++) w[k] = uh[k];
    rot_pass(w, sl, cl, lane);

    load8h(TH + (size_t)b * NP + 256 + lane * 8, tv);
    #pragma unroll
    for (int k = 0; k < 8; k++)
        sincospi_t(fast_tanh(tv[k]), sl[k], cl[k]);
    rot_pass(w, sl, cl, lane);

    float ssq = 0.f, dhr = 0.f, drt = 0.f, dht = 0.f;
    #pragma unroll
    for (int k = 0; k < 8; k++) {
        ssq = fmaf(w[k], w[k], ssq);
        dhr = fmaf(w[k], uh[k], dhr);
        drt = fmaf(w[k], ut[k], drt);
        dht = fmaf(uh[k], ut[k], dht);
    }
    #pragma unroll
    for (int o = 16; o > 0; o >>= 1) {
        ssq += __shfl_xor_sync(FULLM, ssq, o);
        dhr += __shfl_xor_sync(FULLM, dhr, o);
        drt += __shfl_xor_sync(FULLM, drt, o);
        dht += __shfl_xor_sync(FULLM, dht, o);
    }

    if (lane != 0) return;

    float nr = sqrtf(ssq);
    float inv_rot = 1.f / (nr + EPSF);
    float dhr_n = dhr * inv_rot;
    float dotc = fminf(fmaxf(dhr_n, -1.f + EPSF), 1.f - EPSF);
    float omega = acosf(dotc);
    float sin_om = sinf(omega);
    float sv = sim[b];
    float grho = 1.f / (1.f + expf(-(ga_rho[0] * sv + gb_rho[0])));
    float gphi = 1.f / (1.f + expf(-(ga_phi[0] * sv + gb_phi[0])));
    float ca, cb;
    if (omega > DELTAF) {
        float iso = 1.f / (sin_om + EPSF);
        ca = sinf((1.f - gphi) * omega) * iso;
        cb = sinf(gphi * omega) * iso;
    } else {
        ca = 1.f - gphi; cb = gphi;
    }
    float nrn = nr * inv_rot;
    float np2 = ca * ca + cb * cb * nrn * nrn + 2.f * ca * cb * dhr_n;
    float npv = sqrtf(fmaxf(np2, 0.f));
    float inv_np = 1.f / (npv + EPSF);
    float dpt = (ca * dht + cb * drt * inv_rot) * inv_np;

    float rho_h = fminf(softplusf(reh[b]), RHO_MAXF);
    float rho_p = fminf(fmaxf(rho_h + rrr[b] * grho, 0.f), RHO_MAXF);
    float rho_t = fminf(softplusf(ret[b]), RHO_MAXF);
    out[b] = -coshf(rho_p) * coshf(rho_t) + sinhf(rho_p) * sinhf(rho_t) * dpt;
}

// ---------------- launch --------------------------------------------------------------
extern "C" void kernel_launch(void* const* d_in, const int* in_sizes, int n_in,
                              void* d_out, int out_size)
{
    const float* ent  = (const float*)d_in[0];
    const float* rel  = (const float*)d_in[1];
    const float* lab  = (const float*)d_in[2];
    const float* sim  = (const float*)d_in[3];
    const float* Wv   = (const float*)d_in[4];
    const float* bv   = (const float*)d_in[5];
    const float* Wre  = (const float*)d_in[6];
    const float* bre  = (const float*)d_in[7];
    const float* Wrr  = (const float*)d_in[8];
    const float* brr  = (const float*)d_in[9];
    const float* Wt   = (const float*)d_in[10];
    const float* bt   = (const float*)d_in[11];
    const float* ga_rho = (const float*)d_in[12];
    const float* gb_rho = (const float*)d_in[13];
    const float* ga_phi = (const float*)d_in[14];
    const float* gb_phi = (const float*)d_in[15];
    const float* W1   = (const float*)d_in[16];
    const float* b1   = (const float*)d_in[17];
    const float* W2   = (const float*)d_in[18];
    const float* b2   = (const float*)d_in[19];
    float* out = (float*)d_out;

    __half *hEnt, *hRel, *hLab, *hH0, *hH1, *hH2, *hEh, *hEr, *hEt;
    __half *hW1, *hW2, *hWv, *hWt;
    float *reh, *rrr, *ret;
    cudaGetSymbolAddress((void**)&hEnt, g_hEnt);
    cudaGetSymbolAddress((void**)&hRel, g_hRel);
    cudaGetSymbolAddress((void**)&hLab, g_hLab);
    cudaGetSymbolAddress((void**)&hH0,  g_hH0);
    cudaGetSymbolAddress((void**)&hH1,  g_hH1);
    cudaGetSymbolAddress((void**)&hH2,  g_hH2);
    cudaGetSymbolAddress((void**)&hEh,  g_hEh);
    cudaGetSymbolAddress((void**)&hEr,  g_hEr);
    cudaGetSymbolAddress((void**)&hEt,  g_hEt);
    cudaGetSymbolAddress((void**)&hW1,  g_hW1);
    cudaGetSymbolAddress((void**)&hW2,  g_hW2);
    cudaGetSymbolAddress((void**)&hWv,  g_hWv);
    cudaGetSymbolAddress((void**)&hWt,  g_hWt);
    cudaGetSymbolAddress((void**)&reh,  g_reh);
    cudaGetSymbolAddress((void**)&rrr,  g_rrr);
    cudaGetSymbolAddress((void**)&ret,  g_ret);

    cudaFuncSetAttribute(gemm_h, cudaFuncAttributeMaxDynamicSharedMemorySize,
                         GEMM_SMEM_BYTES);

    const int BIG = NB * HD;
    cvt3_f2h<<<dim3(BIG / (256 * 8), 3), 256>>>(ent, rel, lab, hEnt, hRel, hLab);
    cvt_f2h<<<(HD * HD) / (256 * 8), 256>>>(W1, hW1, HD * HD);
    cvt_f2h<<<(HD * HD) / (256 * 8), 256>>>(W2, hW2, HD * HD);
    cvt_f2h<<<(DV * HD) / (256 * 8), 256>>>(Wv, hWv, DV * HD);
    cvt_f2h<<<(NP * HD) / (256 * 8), 256>>>(Wt, hWt, NP * HD);

    const dim3 blk(256);
    // layer 1: hH_z = fp16(relu(X_z @ W1^T + b1))             mode 1|8 = 9
    gemm_h<<<dim3(HD/128, NB/128, 3), blk, GEMM_SMEM_BYTES>>>(
        hEnt, hRel, hLab, hW1, b1, nullptr, nullptr, nullptr,
        hH0, hH1, hH2, HD, 9);
    // layer 2: hE_z = fp16(H_z @ W2^T + b2 + X_z[fp16])       mode 16|8 = 24
    gemm_h<<<dim3(HD/128, NB/128, 3), blk, GEMM_SMEM_BYTES>>>(
        hH0, hH1, hH2, hW2, b2, hEnt, hRel, hLab,
        hEh, hEr, hEt, HD, 24);
    // Wv projections -> fp16 (reuse hH0/hH1)                  mode 8
    gemm_h<<<dim3(DV/128, NB/128, 2), blk, GEMM_SMEM_BYTES>>>(
        hEh, hEt, nullptr, hWv, bv, nullptr, nullptr, nullptr,
        hH0, hH1, nullptr, DV, 8);
    // theta logits -> fp16 (reuse hH2)                        mode 8
    gemm_h<<<dim3(NP/128, NB/128, 1), blk, GEMM_SMEM_BYTES>>>(
        hEr, nullptr, nullptr, hWt, bt, nullptr, nullptr, nullptr,
        hH2, nullptr, nullptr, NP, 8);

    gemv3h<<<NB / 8, 256>>>(hEh, hEr, hEt, Wre, bre, Wrr, brr, reh, rrr, ret);

    // fused warp-per-row: normalize + 512 Givens rotations (affine scan) + score
    polar_score<<<(NB * 32) / 256, 256>>>(hH0, hH1, hH2, sim, reh, rrr, ret,
                                          ga_rho, gb_rho, ga_phi, gb_phi, out);
    (void)in_sizes; (void)n_in; (void)out_size;
}

// round 15
// speedup vs baseline: 1.3621x; 1.0302x over previous
#include <cuda_runtime.h>
#include <cuda_fp16.h>
#include <math.h>
#include <stdint.h>

#define NB 32768
#define HD 512
#define DV 256
#define NP 512
#define RHO_MAXF 9.0f
#define DELTAF 0.001f
#define EPSF 1e-8f
#define PIF 3.14159265358979f

// ---------------- scratch (__device__ globals: no allocations allowed) ----------------
__device__ __half g_hEnt[NB*HD];
__device__ __half g_hRel[NB*HD];
__device__ __half g_hLab[NB*HD];
__device__ __half g_hH0[NB*HD];   // layer-1 hidden; reused as fp16 Vh after layer 2
__device__ __half g_hH1[NB*HD];   // layer-1 hidden; reused as fp16 Vt
__device__ __half g_hH2[NB*HD];   // layer-1 hidden; reused as fp16 TH
__device__ __half g_hEh[NB*HD];
__device__ __half g_hEr[NB*HD];
__device__ __half g_hEt[NB*HD];
__device__ __half g_hW1[HD*HD];
__device__ __half g_hW2[HD*HD];
__device__ __half g_hWv[DV*HD];
__device__ __half g_hWt[NP*HD];

__device__ __forceinline__ float softplusf(float x) {
    return (x > 20.f) ? x : log1pf(expf(x));
}

__device__ __forceinline__ float fast_tanh(float x) {
    float y;
    asm("tanh.approx.f32 %0, %1;" : "=f"(y) : "f"(x));
    return y;
}

// sin(pi*t), cos(pi*t) for t in [-1,1] on the FMA pipe (no MUFU sin/cos, no F2I).
__device__ __forceinline__ void sincospi_t(float t, float& s, float& c) {
    float at = fabsf(t);
    bool f1 = at > 0.5f;
    float b = f1 ? (1.0f - at) : at;
    bool f2 = b > 0.25f;
    float d = f2 ? (0.5f - b) : b;
    float r = d * PIF;
    float w = r * r;
    float ps = fmaf(w, -1.9515296e-4f, 8.3321609e-3f);
    ps = fmaf(w, ps, -1.6666655e-1f);
    float sinr = fmaf(r * w, ps, r);
    float pc = fmaf(w, 2.4433157e-5f, -1.3887316e-3f);
    pc = fmaf(w, pc, 4.1666642e-2f);
    float cosr = fmaf(w * w, pc, fmaf(-0.5f, w, 1.0f));
    float sb = f2 ? cosr : sinr;
    float cb = f2 ? sinr : cosr;
    float ca = f1 ? -cb : cb;
    s = copysignf(sb, t);
    c = ca;
}

#define CP_ASYNC16(dst, src) \
    asm volatile("cp.async.cg.shared.global [%0], [%1], 16;" :: "r"(dst), "l"(src))
#define CP_COMMIT() asm volatile("cp.async.commit_group;" ::: "memory")
#define CP_WAIT2()  asm volatile("cp.async.wait_group 2;" ::: "memory")
#define CP_WAIT1()  asm volatile("cp.async.wait_group 1;" ::: "memory")

#define LDSM4(r0, r1, r2, r3, addr) \
    asm volatile("ldmatrix.sync.aligned.m8n8.x4.shared.b16 {%0,%1,%2,%3}, [%4];" \
                 : "=r"(r0), "=r"(r1), "=r"(r2), "=r"(r3) : "r"(addr))

__device__ __forceinline__ uint32_t smem_u32(const void* p) {
    uint32_t a;
    asm("{ .reg .u64 t; cvta.to.shared.u64 t, %1; cvt.u32.u64 %0, t; }" : "=r"(a) : "l"(p));
    return a;
}

// ---------------- fp32 -> fp16 conversions -------------------------------------------
__global__ void cvt3_f2h(const float* __restrict__ s0, const float* __restrict__ s1,
                         const float* __restrict__ s2,
                         __half* __restrict__ d0, __half* __restrict__ d1,
                         __half* __restrict__ d2)
{
    const float* s = (blockIdx.y == 0) ? s0 : (blockIdx.y == 1) ? s1 : s2;
    __half* d = (blockIdx.y == 0) ? d0 : (blockIdx.y == 1) ? d1 : d2;
    const int i = (blockIdx.x * blockDim.x + threadIdx.x) * 8;
    float4 a = *(const float4*)&s[i];
    float4 b = *(const float4*)&s[i + 4];
    __half2 h0 = __floats2half2_rn(a.x, a.y);
    __half2 h1 = __floats2half2_rn(a.z, a.w);
    __half2 h2 = __floats2half2_rn(b.x, b.y);
    __half2 h3 = __floats2half2_rn(b.z, b.w);
    uint4 o;
    o.x = *(uint32_t*)&h0; o.y = *(uint32_t*)&h1;
    o.z = *(uint32_t*)&h2; o.w = *(uint32_t*)&h3;
    *(uint4*)&d[i] = o;
}

// all 4 weight tensors in one launch (y selects tensor; x guarded by per-tensor size)
__global__ void cvtW_f2h(const float* __restrict__ s0, const float* __restrict__ s1,
                         const float* __restrict__ s2, const float* __restrict__ s3,
                         __half* __restrict__ d0, __half* __restrict__ d1,
                         __half* __restrict__ d2, __half* __restrict__ d3)
{
    const int y = blockIdx.y;
    const float* s = (y == 0) ? s0 : (y == 1) ? s1 : (y == 2) ? s2 : s3;
    __half* d = (y == 0) ? d0 : (y == 1) ? d1 : (y == 2) ? d2 : d3;
    const int n = (y == 2) ? (DV * HD) : (HD * HD);
    const int i = (blockIdx.x * blockDim.x + threadIdx.x) * 8;
    if (i >= n) return;
    float4 a = *(const float4*)&s[i];
    float4 b = *(const float4*)&s[i + 4];
    __half2 h0 = __floats2half2_rn(a.x, a.y);
    __half2 h1 = __floats2half2_rn(a.z, a.w);
    __half2 h2 = __floats2half2_rn(b.x, b.y);
    __half2 h3 = __floats2half2_rn(b.z, b.w);
    uint4 o;
    o.x = *(uint32_t*)&h0; o.y = *(uint32_t*)&h1;
    o.z = *(uint32_t*)&h2; o.w = *(uint32_t*)&h3;
    *(uint4*)&d[i] = o;
}

// ---------------- FP16 tensor-core NT GEMM (R9 baseline mainloop) --------------------
// mode bits: 1=relu, 16=+residual fp16(R), 8=store fp16 Ch
#define SMS 20
#define KDIM 512
#define KT 32
#define NKT (KDIM / KT)
#define SA_WORDS (128 * SMS)
#define STG_WORDS (2 * SA_WORDS)
#define STG_BYTES (STG_WORDS * 4)
#define GEMM_SMEM_BYTES (3 * STG_BYTES)

__global__ __launch_bounds__(256, 2)
void gemm_h(const __half* __restrict__ A0, const __half* __restrict__ A1,
            const __half* __restrict__ A2,
            const __half* __restrict__ W, const float* __restrict__ bias,
            const __half* __restrict__ R0, const __half* __restrict__ R1,
            const __half* __restrict__ R2,
            __half* __restrict__ Ch0, __half* __restrict__ Ch1, __half* __restrict__ Ch2,
            int N, int mode)
{
    extern __shared__ __align__(16) uint32_t smem[];
    const int tid = threadIdx.x, wid = tid >> 5, lane = tid & 31;
    const int g = lane >> 2, tg = lane & 3;
    const int z = blockIdx.z;
    const __half* A = (z == 0) ? A0 : (z == 1) ? A1 : A2;
    const __half* R = (z == 0) ? R0 : (z == 1) ? R1 : R2;
    __half*      Ch = (z == 0) ? Ch0 : (z == 1) ? Ch1 : Ch2;
    const int m0 = blockIdx.y * 128;
    const int n0 = blockIdx.x * 128;
    const int moff = (wid & 3) * 32;
    const int noff = (wid >> 2) * 64;
    const __half* Ag = A + (size_t)m0 * KDIM;
    const __half* Bg = W + (size_t)n0 * KDIM;

    const uint32_t sbase = smem_u32(smem);

    const int lrow8 = ((lane >> 3) & 1) * 8 + (lane & 7);
    const int lk4   = (lane >> 4) * 4;
    uint32_t aoff[2], boff[4];
    #pragma unroll
    for (int mt = 0; mt < 2; mt++)
        aoff[mt] = ((moff + mt * 16 + lrow8) * SMS + lk4) * 4;
    #pragma unroll
    for (int ntp = 0; ntp < 4; ntp++)
        boff[ntp] = ((noff + ntp * 16 + lrow8) * SMS + lk4) * 4;

    float acc[2][8][4];
    #pragma unroll
    for (int mt = 0; mt < 2; mt++)
        #pragma unroll
        for (int nt = 0; nt < 8; nt++)
            #pragma unroll
            for (int q = 0; q < 4; q++) acc[mt][nt][q] = 0.f;

    #define FILL_STAGE(stg, k0)                                                      \
    do {                                                                             \
        const uint32_t wA = sbase + (stg) * STG_BYTES;                               \
        const uint32_t wB = wA + SA_WORDS * 4;                                       \
        _Pragma("unroll")                                                            \
        for (int p = 0; p < 2; p++) {                                                \
            const int c = tid + 256 * p;                                             \
            const int row = c >> 2;                                                  \
            CP_ASYNC16(wA + (row * SMS + (c & 3) * 4) * 4,                           \
                       &Ag[(size_t)row * KDIM + (k0) + (c & 3) * 8]);                \
            CP_ASYNC16(wB + (row * SMS + (c & 3) * 4) * 4,                           \
                       &Bg[(size_t)row * KDIM + (k0) + (c & 3) * 8]);                \
        }                                                                            \
    } while (0)

    FILL_STAGE(0, 0);  CP_COMMIT();
    FILL_STAGE(1, KT); CP_COMMIT();
    CP_WAIT1();
    __syncthreads();

    for (int t = 0; t < NKT; t++) {
        if (t + 2 < NKT) { FILL_STAGE((t + 2) % 3, (t + 2) * KT); }
        CP_COMMIT();
        CP_WAIT2();
        __syncthreads();

        const uint32_t Ab = sbase + (t % 3) * STG_BYTES;
        const uint32_t Bb = Ab + SA_WORDS * 4;

        #pragma unroll
        for (int ks = 0; ks < 2; ks++) {
            const uint32_t kb4 = ks * 32;
            uint32_t af[2][4], bf[8][2];
            #pragma unroll
            for (int mt = 0; mt < 2; mt++)
                LDSM4(af[mt][0], af[mt][1], af[mt][2], af[mt][3], Ab + aoff[mt] + kb4);
            #pragma unroll
            for (int ntp = 0; ntp < 4; ntp++)
                LDSM4(bf[2*ntp][0], bf[2*ntp+1][0], bf[2*ntp][1], bf[2*ntp+1][1],
                      Bb + boff[ntp] + kb4);
            #pragma unroll
            for (int mt = 0; mt < 2; mt++)
                #pragma unroll
                for (int nt = 0; nt < 8; nt++) {
                    asm volatile(
                        "mma.sync.aligned.m16n8k16.row.col.f32.f16.f16.f32 "
                        "{%0,%1,%2,%3}, {%4,%5,%6,%7}, {%8,%9}, {%0,%1,%2,%3};"
                        : "+f"(acc[mt][nt][0]), "+f"(acc[mt][nt][1]),
                          "+f"(acc[mt][nt][2]), "+f"(acc[mt][nt][3])
                        : "r"(af[mt][0]), "r"(af[mt][1]), "r"(af[mt][2]), "r"(af[mt][3]),
                          "r"(bf[nt][0]), "r"(bf[nt][1]));
                }
        }
        __syncthreads();
    }

    // ---- epilogue ----
    #pragma unroll
    for (int mt = 0; mt < 2; mt++) {
        #pragma unroll
        for (int nt = 0; nt < 8; nt++) {
            const int n = n0 + noff + nt * 8 + 2 * tg;
            const int ra = m0 + moff + mt * 16 + g;
            const int rb = ra + 8;
            float bx = bias[n], by = bias[n + 1];
            float2 v0 = make_float2(acc[mt][nt][0] + bx, acc[mt][nt][1] + by);
            float2 v1 = make_float2(acc[mt][nt][2] + bx, acc[mt][nt][3] + by);
            if (mode & 1) {
                v0.x = fmaxf(v0.x, 0.f); v0.y = fmaxf(v0.y, 0.f);
                v1.x = fmaxf(v1.x, 0.f); v1.y = fmaxf(v1.y, 0.f);
            }
            if (mode & 16) {
                float2 r0v = __half22float2(*(const __half2*)&R[(size_t)ra * N + n]);
                float2 r1v = __half22float2(*(const __half2*)&R[(size_t)rb * N + n]);
                v0.x += r0v.x; v0.y += r0v.y;
                v1.x += r1v.x; v1.y += r1v.y;
            }
            if (mode & 8) {
                __half2 h0 = __floats2half2_rn(v0.x, v0.y);
                __half2 h1 = __floats2half2_rn(v1.x, v1.y);
                *(__half2*)&Ch[(size_t)ra * N + n] = h0;
                *(__half2*)&Ch[(size_t)rb * N + n] = h1;
            }
        }
    }
}

// ================== warp-per-row fused gemv + polar + rotation-scan + score ==========
#define FULLM 0xffffffffu

__device__ __forceinline__ void rot_pass(float* xl, const float* sl, const float* cl,
                                         int lane)
{
    float x0 = __shfl_sync(FULLM, xl[0], 0);
    float x1 = __shfl_sync(FULLM, xl[1], 0);
    float s0 = __shfl_sync(FULLM, sl[0], 0);
    float c0 = __shfl_sync(FULLM, cl[0], 0);
    float x0pre = c0 * x0 - s0 * x1;

    float nx[8];
    #pragma unroll
    for (int k = 0; k < 7; k++) nx[k] = xl[k + 1];
    nx[7] = __shfl_down_sync(FULLM, xl[0], 1);
    if (lane == 31) nx[7] = x0pre;

    float A = 1.f, B = 0.f;
    #pragma unroll
    for (int k = 0; k < 8; k++) {
        B = fmaf(sl[k], B, cl[k] * nx[k]);
        A *= sl[k];
    }
    #pragma unroll
    for (int d = 1; d < 32; d <<= 1) {
        float pA = __shfl_up_sync(FULLM, A, d);
        float pB = __shfl_up_sync(FULLM, B, d);
        if (lane >= d) {
            B = fmaf(A, pB, B);
            A *= pA;
        }
    }
    float eA = __shfl_up_sync(FULLM, A, 1);
    float eB = __shfl_up_sync(FULLM, B, 1);
    if (lane == 0) { eA = 1.f; eB = 0.f; }
    float cur = fmaf(eA, x0, eB);

    float w[8];
    #pragma unroll
    for (int k = 0; k < 8; k++) {
        w[k] = cl[k] * cur - sl[k] * nx[k];
        cur = fmaf(sl[k], cur, cl[k] * nx[k]);
    }
    float x0fin = __shfl_sync(FULLM, cur, 31);
    #pragma unroll
    for (int k = 0; k < 8; k++) xl[k] = w[k];
    if (lane == 0) xl[0] = x0fin;
}

__device__ __forceinline__ void load8h(const __half* p, float* v) {
    uint4 a = *(const uint4*)p;
    const __half2* hp = (const __half2*)&a;
    float2 f0 = __half22float2(hp[0]);
    float2 f1 = __half22float2(hp[1]);
    float2 f2 = __half22float2(hp[2]);
    float2 f3 = __half22float2(hp[3]);
    v[0]=f0.x; v[1]=f0.y; v[2]=f1.x; v[3]=f1.y;
    v[4]=f2.x; v[5]=f2.y; v[6]=f3.x; v[7]=f3.y;
}

__global__ __launch_bounds__(256)
void polar_score(const __half* __restrict__ Vh, const __half* __restrict__ Vt,
                 const __half* __restrict__ TH,
                 const __half* __restrict__ Eh, const __half* __restrict__ Er,
                 const __half* __restrict__ Et,
                 const float* __restrict__ Wre, const float* __restrict__ bre,
                 const float* __restrict__ Wrr, const float* __restrict__ brr,
                 const float* __restrict__ sim,
                 const float* __restrict__ ga_rho, const float* __restrict__ gb_rho,
                 const float* __restrict__ ga_phi, const float* __restrict__ gb_phi,
                 float* __restrict__ out)
{
    const int b = (blockIdx.x * blockDim.x + threadIdx.x) >> 5;
    const int lane = threadIdx.x & 31;
    if (b >= NB) return;

    // ---- fused gemv: s1 = Eh.Wre, s2 = Er.Wrr, s3 = Et.Wre (16 elems/lane) ----
    float s1 = 0.f, s2 = 0.f, s3 = 0.f;
    {
        const int k0 = lane * 16;
        float e[8], wv[8];
        #pragma unroll
        for (int hseg = 0; hseg < 2; hseg++) {
            const int k = k0 + hseg * 8;
            #pragma unroll
            for (int j = 0; j < 8; j += 4)
                *(float4*)&wv[j] = *(const float4*)&Wre[k + j];
            load8h(Eh + (size_t)b * HD + k, e);
            #pragma unroll
            for (int j = 0; j < 8; j++) s1 = fmaf(e[j], wv[j], s1);
            load8h(Et + (size_t)b * HD + k, e);
            #pragma unroll
            for (int j = 0; j < 8; j++) s3 = fmaf(e[j], wv[j], s3);
            #pragma unroll
            for (int j = 0; j < 8; j += 4)
                *(float4*)&wv[j] = *(const float4*)&Wrr[k + j];
            load8h(Er + (size_t)b * HD + k, e);
            #pragma unroll
            for (int j = 0; j < 8; j++) s2 = fmaf(e[j], wv[j], s2);
        }
    }

    // ---- load u_h, u_t + norms ----
    float uh[8], ut[8];
    load8h(Vh + (size_t)b * DV + lane * 8, uh);
    load8h(Vt + (size_t)b * DV + lane * 8, ut);

    float nh = 0.f, nt2 = 0.f;
    #pragma unroll
    for (int k = 0; k < 8; k++) { nh = fmaf(uh[k], uh[k], nh); nt2 = fmaf(ut[k], ut[k], nt2); }
    #pragma unroll
    for (int o = 16; o > 0; o >>= 1) {
        nh  += __shfl_xor_sync(FULLM, nh,  o);
        nt2 += __shfl_xor_sync(FULLM, nt2, o);
    }
    float ih = 1.f / (sqrtf(nh) + EPSF);
    float it = 1.f / (sqrtf(nt2) + EPSF);
    #pragma unroll
    for (int k = 0; k < 8; k++) { uh[k] *= ih; ut[k] *= it; }

    // ---- rotations ----
    float sl[8], cl[8], tv[8];
    load8h(TH + (size_t)b * NP + lane * 8, tv);
    #pragma unroll
    for (int k = 0; k < 8; k++)
        sincospi_t(fast_tanh(tv[k]), sl[k], cl[k]);

    float w[8];
    #pragma unroll
    for (int k = 0; k < 8; k++) w[k] = uh[k];
    rot_pass(w, sl, cl, lane);

    load8h(TH + (size_t)b * NP + 256 + lane * 8, tv);
    #pragma unroll
    for (int k = 0; k < 8; k++)
        sincospi_t(fast_tanh(tv[k]), sl[k], cl[k]);
    rot_pass(w, sl, cl, lane);

    // ---- dots + combined reduction (incl. gemv partials) ----
    float ssq = 0.f, dhr = 0.f, drt = 0.f, dht = 0.f;
    #pragma unroll
    for (int k = 0; k < 8; k++) {
        ssq = fmaf(w[k], w[k], ssq);
        dhr = fmaf(w[k], uh[k], dhr);
        drt = fmaf(w[k], ut[k], drt);
        dht = fmaf(uh[k], ut[k], dht);
    }
    #pragma unroll
    for (int o = 16; o > 0; o >>= 1) {
        ssq += __shfl_xor_sync(FULLM, ssq, o);
        dhr += __shfl_xor_sync(FULLM, dhr, o);
        drt += __shfl_xor_sync(FULLM, drt, o);
        dht += __shfl_xor_sync(FULLM, dht, o);
        s1  += __shfl_xor_sync(FULLM, s1,  o);
        s2  += __shfl_xor_sync(FULLM, s2,  o);
        s3  += __shfl_xor_sync(FULLM, s3,  o);
    }

    if (lane != 0) return;

    float nr = sqrtf(ssq);
    float inv_rot = 1.f / (nr + EPSF);
    float dhr_n = dhr * inv_rot;
    float dotc = fminf(fmaxf(dhr_n, -1.f + EPSF), 1.f - EPSF);
    float omega = acosf(dotc);
    float sin_om = sinf(omega);
    float sv = sim[b];
    float grho = 1.f / (1.f + expf(-(ga_rho[0] * sv + gb_rho[0])));
    float gphi = 1.f / (1.f + expf(-(ga_phi[0] * sv + gb_phi[0])));
    float ca, cb;
    if (omega > DELTAF) {
        float iso = 1.f / (sin_om + EPSF);
        ca = sinf((1.f - gphi) * omega) * iso;
        cb = sinf(gphi * omega) * iso;
    } else {
        ca = 1.f - gphi; cb = gphi;
    }
    float nrn = nr * inv_rot;
    float np2 = ca * ca + cb * cb * nrn * nrn + 2.f * ca * cb * dhr_n;
    float npv = sqrtf(fmaxf(np2, 0.f));
    float inv_np = 1.f / (npv + EPSF);
    float dpt = (ca * dht + cb * drt * inv_rot) * inv_np;

    float reh_v = s1 + bre[0];
    float rrr_v = s2 + brr[0];
    float ret_v = s3 + bre[0];
    float rho_h = fminf(softplusf(reh_v), RHO_MAXF);
    float rho_p = fminf(fmaxf(rho_h + rrr_v * grho, 0.f), RHO_MAXF);
    float rho_t = fminf(softplusf(ret_v), RHO_MAXF);
    out[b] = -coshf(rho_p) * coshf(rho_t) + sinhf(rho_p) * sinhf(rho_t) * dpt;
}

// ---------------- launch --------------------------------------------------------------
extern "C" void kernel_launch(void* const* d_in, const int* in_sizes, int n_in,
                              void* d_out, int out_size)
{
    const float* ent  = (const float*)d_in[0];
    const float* rel  = (const float*)d_in[1];
    const float* lab  = (const float*)d_in[2];
    const float* sim  = (const float*)d_in[3];
    const float* Wv   = (const float*)d_in[4];
    const float* bv   = (const float*)d_in[5];
    const float* Wre  = (const float*)d_in[6];
    const float* bre  = (const float*)d_in[7];
    const float* Wrr  = (const float*)d_in[8];
    const float* brr  = (const float*)d_in[9];
    const float* Wt   = (const float*)d_in[10];
    const float* bt   = (const float*)d_in[11];
    const float* ga_rho = (const float*)d_in[12];
    const float* gb_rho = (const float*)d_in[13];
    const float* ga_phi = (const float*)d_in[14];
    const float* gb_phi = (const float*)d_in[15];
    const float* W1   = (const float*)d_in[16];
    const float* b1   = (const float*)d_in[17];
    const float* W2   = (const float*)d_in[18];
    const float* b2   = (const float*)d_in[19];
    float* out = (float*)d_out;

    __half *hEnt, *hRel, *hLab, *hH0, *hH1, *hH2, *hEh, *hEr, *hEt;
    __half *hW1, *hW2, *hWv, *hWt;
    cudaGetSymbolAddress((void**)&hEnt, g_hEnt);
    cudaGetSymbolAddress((void**)&hRel, g_hRel);
    cudaGetSymbolAddress((void**)&hLab, g_hLab);
    cudaGetSymbolAddress((void**)&hH0,  g_hH0);
    cudaGetSymbolAddress((void**)&hH1,  g_hH1);
    cudaGetSymbolAddress((void**)&hH2,  g_hH2);
    cudaGetSymbolAddress((void**)&hEh,  g_hEh);
    cudaGetSymbolAddress((void**)&hEr,  g_hEr);
    cudaGetSymbolAddress((void**)&hEt,  g_hEt);
    cudaGetSymbolAddress((void**)&hW1,  g_hW1);
    cudaGetSymbolAddress((void**)&hW2,  g_hW2);
    cudaGetSymbolAddress((void**)&hWv,  g_hWv);
    cudaGetSymbolAddress((void**)&hWt,  g_hWt);

    cudaFuncSetAttribute(gemm_h, cudaFuncAttributeMaxDynamicSharedMemorySize,
                         GEMM_SMEM_BYTES);

    const int BIG = NB * HD;
    cvt3_f2h<<<dim3(BIG / (256 * 8), 3), 256>>>(ent, rel, lab, hEnt, hRel, hLab);
    cvtW_f2h<<<dim3((HD * HD) / (256 * 8), 4), 256>>>(W1, W2, Wv, Wt,
                                                      hW1, hW2, hWv, hWt);

    const dim3 blk(256);
    // layer 1: hH_z = fp16(relu(X_z @ W1^T + b1))             mode 1|8 = 9
    gemm_h<<<dim3(HD/128, NB/128, 3), blk, GEMM_SMEM_BYTES>>>(
        hEnt, hRel, hLab, hW1, b1, nullptr, nullptr, nullptr,
        hH0, hH1, hH2, HD, 9);
    // layer 2: hE_z = fp16(H_z @ W2^T + b2 + X_z[fp16])       mode 16|8 = 24
    gemm_h<<<dim3(HD/128, NB/128, 3), blk, GEMM_SMEM_BYTES>>>(
        hH0, hH1, hH2, hW2, b2, hEnt, hRel, hLab,
        hEh, hEr, hEt, HD, 24);
    // Wv projections -> fp16 (reuse hH0/hH1)                  mode 8
    gemm_h<<<dim3(DV/128, NB/128, 2), blk, GEMM_SMEM_BYTES>>>(
        hEh, hEt, nullptr, hWv, bv, nullptr, nullptr, nullptr,
        hH0, hH1, nullptr, DV, 8);
    // theta logits -> fp16 (reuse hH2)                        mode 8
    gemm_h<<<dim3(NP/128, NB/128, 1), blk, GEMM_SMEM_BYTES>>>(
        hEr, nullptr, nullptr, hWt, bt, nullptr, nullptr, nullptr,
        hH2, nullptr, nullptr, NP, 8);

    // fused warp-per-row: gemv (rho logits) + normalize + Givens scan + score
    polar_score<<<(NB * 32) / 256, 256>>>(hH0, hH1, hH2, hEh, hEr, hEt,
                                          Wre, bre, Wrr, brr, sim,
                                          ga_rho, gb_rho, ga_phi, gb_phi, out);
    (void)in_sizes; (void)n_in; (void)out_size;
}